// round 6
// baseline (speedup 1.0000x reference)
#include <cuda_runtime.h>
#include <cstdint>

#define NNODES 50000
#define NEDGES 800000
#define FDIM 64
#define NCLS 40
#define NLAYER 3

// ---------------- device scratch (no allocations allowed) ----------------
__device__ __align__(16) float g_agg[NNODES * FDIM];
__device__ __align__(16) float g_xA[NNODES * FDIM];
__device__ __align__(16) float g_xB[NNODES * FDIM];
__device__ __align__(16) float g_W1f[NLAYER * FDIM * 128];   // 3 x 64 x 128
__device__ __align__(16) float g_b1f[NLAYER * 128];
__device__ __align__(16) float g_W2f[NLAYER * 128 * FDIM];   // 3 x 128 x 64
__device__ __align__(16) float g_b2f[NLAYER * FDIM];
__device__ __align__(16) float g_lin1f[FDIM * FDIM];
__device__ __align__(16) float g_b1hf[FDIM];

// ---------------- BN folding ----------------
__global__ void prep_kernel(
    const float* __restrict__ W1s, const float* __restrict__ b1s,
    const float* __restrict__ g1s, const float* __restrict__ bt1s,
    const float* __restrict__ m1s, const float* __restrict__ v1s,
    const float* __restrict__ W2s, const float* __restrict__ b2s,
    const float* __restrict__ gcs, const float* __restrict__ bcs,
    const float* __restrict__ mcs, const float* __restrict__ vcs,
    const float* __restrict__ lin1_W, const float* __restrict__ lin1_b,
    const float* __restrict__ g_bn1, const float* __restrict__ b_bn1,
    const float* __restrict__ m_bn1, const float* __restrict__ v_bn1)
{
    const float eps = 1e-5f;
    int t = blockIdx.x * blockDim.x + threadIdx.x;
    if (t < NLAYER * FDIM * 128) {                     // W1f: 24576
        int l = t / (FDIM * 128);
        int rem = t % (FDIM * 128);
        int j = rem % 128;
        float a = g1s[l * 128 + j] * rsqrtf(v1s[l * 128 + j] + eps);
        g_W1f[t] = W1s[t] * a;
        if (rem < 128)
            g_b1f[l * 128 + rem] =
                (b1s[l * 128 + rem] - m1s[l * 128 + rem]) * a + bt1s[l * 128 + rem];
    } else if (t < 24576 + NLAYER * 128 * FDIM) {      // W2f: 24576
        int u = t - 24576;
        int l = u / (128 * FDIM);
        int rem = u % (128 * FDIM);
        int j = rem % FDIM;
        float a = gcs[l * FDIM + j] * rsqrtf(vcs[l * FDIM + j] + eps);
        g_W2f[u] = W2s[u] * a;
        if (rem < FDIM)
            g_b2f[l * FDIM + rem] =
                (b2s[l * FDIM + rem] - mcs[l * FDIM + rem]) * a + bcs[l * FDIM + rem];
    } else if (t < 49152 + FDIM * FDIM) {              // lin1f: 4096
        int u = t - 49152;
        int j = u % FDIM;
        float a = g_bn1[j] * rsqrtf(v_bn1[j] + eps);
        g_lin1f[u] = lin1_W[u] * a;
        if (u < FDIM)
            g_b1hf[u] = (lin1_b[u] - m_bn1[u]) * a + b_bn1[u];
    }
}

// ---------------- edge scatter: agg[dst] += x[src] (agg preinit to x) ----------------
// edge_index delivered by harness as int32 (harness converts int64 -> int32).
__global__ void scatter_kernel(const int* __restrict__ ei,
                               const float* __restrict__ x)
{
    int t = blockIdx.x * blockDim.x + threadIdx.x;
    if (t >= NEDGES * 16) return;
    int e = t >> 4;
    int q = t & 15;
    int s = __ldg(&ei[e]);
    int d = __ldg(&ei[NEDGES + e]);
    if ((unsigned)s >= NNODES || (unsigned)d >= NNODES) return;  // safety guard
    float4 v = __ldg((const float4*)x + (size_t)s * 16 + q);
    float* p = g_agg + (size_t)d * FDIM + q * 4;
    asm volatile("red.global.add.v4.f32 [%0], {%1,%2,%3,%4};"
                 :: "l"(p), "f"(v.x), "f"(v.y), "f"(v.z), "f"(v.w)
                 : "memory");
}

// ---------------- fused GIN MLP: relu(bn2(W2 @ relu(bn1(W1 @ h)))) ----------------
// 64-node tile per CTA, 512 threads, dynamic smem.
#define MLP_SMEM_FLOATS (8192 + 8192 + 4096 + 8192 + 128 + 64)
__global__ void mlp_kernel(const float* __restrict__ W1f, const float* __restrict__ b1f,
                           const float* __restrict__ W2f, const float* __restrict__ b2f,
                           float* __restrict__ xout)
{
    extern __shared__ float smem[];
    float* sW1 = smem;            // 64x128
    float* sW2 = sW1 + 8192;      // 128x64
    float* sh  = sW2 + 8192;      // 64x64
    float* st  = sh + 4096;       // 64x128
    float* sB1 = st + 8192;       // 128
    float* sB2 = sB1 + 128;       // 64

    int tid = threadIdx.x;        // 512 threads
    int node0 = blockIdx.x * 64;

    for (int i = tid; i < 8192; i += 512) { sW1[i] = W1f[i]; sW2[i] = W2f[i]; }
    if (tid < 128) sB1[tid] = b1f[tid];
    else if (tid < 192) sB2[tid - 128] = b2f[tid - 128];
    for (int i = tid; i < 4096; i += 512) {
        int node = node0 + (i >> 6);
        sh[i] = (node < NNODES) ? g_agg[(size_t)node * FDIM + (i & 63)] : 0.f;
    }
    __syncthreads();

    // stage 1: t[64x128] = relu(h @ W1f + b1f); 2 rows x 8 cols per thread
    {
        int rb = (tid >> 4) * 2;
        int cb = (tid & 15) * 8;
        float acc[2][8];
        #pragma unroll
        for (int i = 0; i < 2; i++)
            #pragma unroll
            for (int j = 0; j < 8; j++) acc[i][j] = sB1[cb + j];
        #pragma unroll 4
        for (int k = 0; k < 64; k++) {
            float w[8];
            #pragma unroll
            for (int j = 0; j < 8; j++) w[j] = sW1[k * 128 + cb + j];
            #pragma unroll
            for (int i = 0; i < 2; i++) {
                float hv = sh[(rb + i) * 64 + k];
                #pragma unroll
                for (int j = 0; j < 8; j++) acc[i][j] = fmaf(hv, w[j], acc[i][j]);
            }
        }
        #pragma unroll
        for (int i = 0; i < 2; i++)
            #pragma unroll
            for (int j = 0; j < 8; j++)
                st[(rb + i) * 128 + cb + j] = fmaxf(acc[i][j], 0.f);
    }
    __syncthreads();

    // stage 2: out[64x64] = relu(t @ W2f + b2f); 2 rows x 4 cols per thread
    {
        int rb = (tid >> 4) * 2;
        int cb = (tid & 15) * 4;
        float acc[2][4];
        #pragma unroll
        for (int i = 0; i < 2; i++)
            #pragma unroll
            for (int j = 0; j < 4; j++) acc[i][j] = sB2[cb + j];
        #pragma unroll 4
        for (int k = 0; k < 128; k++) {
            float w[4];
            #pragma unroll
            for (int j = 0; j < 4; j++) w[j] = sW2[k * 64 + cb + j];
            #pragma unroll
            for (int i = 0; i < 2; i++) {
                float tv = st[(rb + i) * 128 + k];
                #pragma unroll
                for (int j = 0; j < 4; j++) acc[i][j] = fmaf(tv, w[j], acc[i][j]);
            }
        }
        #pragma unroll
        for (int i = 0; i < 2; i++) {
            int node = node0 + rb + i;
            if (node < NNODES) {
                float4 o = make_float4(fmaxf(acc[i][0], 0.f), fmaxf(acc[i][1], 0.f),
                                       fmaxf(acc[i][2], 0.f), fmaxf(acc[i][3], 0.f));
                *(float4*)(xout + (size_t)node * FDIM + cb) = o;
            }
        }
    }
}

// ---------------- head: relu(bn1(lin1 @ x)) -> lin2 -> log_softmax ----------------
#define HEAD_SMEM_FLOATS (4096 + 2560 + 4096 + 4096 + 2560 + 64 + 40 + 64 + 64)
__global__ void head_kernel(const float* __restrict__ xin,
                            const float* __restrict__ lin2_W,
                            const float* __restrict__ lin2_b,
                            float* __restrict__ out)
{
    extern __shared__ float smem[];
    float* sW1  = smem;            // 64x64 folded lin1
    float* sW2  = sW1 + 4096;      // 64x40
    float* sh   = sW2 + 2560;      // 64x64 input tile
    float* sh1  = sh + 4096;       // 64x64 hidden
    float* slog = sh1 + 4096;      // 64x40 logits
    float* sB1  = slog + 2560;     // 64
    float* sB2  = sB1 + 64;        // 40
    float* rmax = sB2 + 40;        // 64
    float* rlse = rmax + 64;       // 64

    int tid = threadIdx.x;         // 512
    int node0 = blockIdx.x * 64;

    for (int i = tid; i < 4096; i += 512) sW1[i] = g_lin1f[i];
    for (int i = tid; i < 2560; i += 512) sW2[i] = lin2_W[i];
    if (tid < 64) sB1[tid] = g_b1hf[tid];
    else if (tid < 104) sB2[tid - 64] = lin2_b[tid - 64];
    for (int i = tid; i < 4096; i += 512) {
        int node = node0 + (i >> 6);
        sh[i] = (node < NNODES) ? xin[(size_t)node * FDIM + (i & 63)] : 0.f;
    }
    __syncthreads();

    // stage 1: h1 = relu(x @ lin1f + b); 2 rows x 4 cols per thread
    {
        int rb = (tid >> 4) * 2;
        int cb = (tid & 15) * 4;
        float acc[2][4];
        #pragma unroll
        for (int i = 0; i < 2; i++)
            #pragma unroll
            for (int j = 0; j < 4; j++) acc[i][j] = sB1[cb + j];
        #pragma unroll 4
        for (int k = 0; k < 64; k++) {
            float w[4];
            #pragma unroll
            for (int j = 0; j < 4; j++) w[j] = sW1[k * 64 + cb + j];
            #pragma unroll
            for (int i = 0; i < 2; i++) {
                float hv = sh[(rb + i) * 64 + k];
                #pragma unroll
                for (int j = 0; j < 4; j++) acc[i][j] = fmaf(hv, w[j], acc[i][j]);
            }
        }
        #pragma unroll
        for (int i = 0; i < 2; i++)
            #pragma unroll
            for (int j = 0; j < 4; j++)
                sh1[(rb + i) * 64 + cb + j] = fmaxf(acc[i][j], 0.f);
    }
    __syncthreads();

    // stage 2: logits = h1 @ lin2 + b; 1 row x 5 cols per thread
    {
        int r = tid >> 3;
        int c0 = (tid & 7) * 5;
        float acc[5];
        #pragma unroll
        for (int j = 0; j < 5; j++) acc[j] = sB2[c0 + j];
        #pragma unroll 4
        for (int k = 0; k < 64; k++) {
            float hv = sh1[r * 64 + k];
            #pragma unroll
            for (int j = 0; j < 5; j++) acc[j] = fmaf(hv, sW2[k * 40 + c0 + j], acc[j]);
        }
        #pragma unroll
        for (int j = 0; j < 5; j++) slog[r * 40 + c0 + j] = acc[j];
    }
    __syncthreads();

    // row stats
    if (tid < 64) {
        float m = -3.4e38f;
        #pragma unroll 8
        for (int c = 0; c < NCLS; c++) m = fmaxf(m, slog[tid * 40 + c]);
        float s = 0.f;
        #pragma unroll 8
        for (int c = 0; c < NCLS; c++) s += expf(slog[tid * 40 + c] - m);
        rmax[tid] = m;
        rlse[tid] = logf(s);
    }
    __syncthreads();

    for (int i = tid; i < 64 * NCLS; i += 512) {
        int r = i / NCLS;
        int node = node0 + r;
        if (node < NNODES)
            out[(size_t)node * NCLS + (i % NCLS)] = slog[i] - rmax[r] - rlse[r];
    }
}

// ---------------- launcher ----------------
extern "C" void kernel_launch(void* const* d_in, const int* in_sizes, int n_in,
                              void* d_out, int out_size)
{
    const float* x     = (const float*)d_in[0];
    const int*   ei    = (const int*)d_in[1];   // int64 in reference -> int32 from harness
    const float* W1s   = (const float*)d_in[2];
    const float* b1s   = (const float*)d_in[3];
    const float* g1s   = (const float*)d_in[4];
    const float* bt1s  = (const float*)d_in[5];
    const float* m1s   = (const float*)d_in[6];
    const float* v1s   = (const float*)d_in[7];
    const float* W2s   = (const float*)d_in[8];
    const float* b2s   = (const float*)d_in[9];
    const float* gcs   = (const float*)d_in[10];
    const float* bcs   = (const float*)d_in[11];
    const float* mcs   = (const float*)d_in[12];
    const float* vcs   = (const float*)d_in[13];
    const float* lin1_W = (const float*)d_in[14];
    const float* lin1_b = (const float*)d_in[15];
    const float* g_bn1 = (const float*)d_in[16];
    const float* b_bn1 = (const float*)d_in[17];
    const float* m_bn1 = (const float*)d_in[18];
    const float* v_bn1 = (const float*)d_in[19];
    const float* lin2_W = (const float*)d_in[20];
    const float* lin2_b = (const float*)d_in[21];

    float *aggp, *xAp, *xBp, *W1fp, *b1fp, *W2fp, *b2fp;
    cudaGetSymbolAddress((void**)&aggp, g_agg);
    cudaGetSymbolAddress((void**)&xAp,  g_xA);
    cudaGetSymbolAddress((void**)&xBp,  g_xB);
    cudaGetSymbolAddress((void**)&W1fp, g_W1f);
    cudaGetSymbolAddress((void**)&b1fp, g_b1f);
    cudaGetSymbolAddress((void**)&W2fp, g_W2f);
    cudaGetSymbolAddress((void**)&b2fp, g_b2f);

    cudaFuncSetAttribute(mlp_kernel, cudaFuncAttributeMaxDynamicSharedMemorySize,
                         MLP_SMEM_FLOATS * 4);
    cudaFuncSetAttribute(head_kernel, cudaFuncAttributeMaxDynamicSharedMemorySize,
                         HEAD_SMEM_FLOATS * 4);

    prep_kernel<<<(53280 + 255) / 256, 256>>>(W1s, b1s, g1s, bt1s, m1s, v1s,
                                              W2s, b2s, gcs, bcs, mcs, vcs,
                                              lin1_W, lin1_b, g_bn1, b_bn1, m_bn1, v_bn1);

    const int nblk = (NNODES + 63) / 64;
    const float* xin = x;
    float* bufs[2] = { xAp, xBp };
    for (int l = 0; l < NLAYER; l++) {
        cudaMemcpyAsync(aggp, xin, (size_t)NNODES * FDIM * sizeof(float),
                        cudaMemcpyDeviceToDevice);
        scatter_kernel<<<(NEDGES * 16 + 255) / 256, 256>>>(ei, xin);
        mlp_kernel<<<nblk, 512, MLP_SMEM_FLOATS * 4>>>(
            W1fp + l * 8192, b1fp + l * 128, W2fp + l * 8192, b2fp + l * 64,
            bufs[l & 1]);
        xin = bufs[l & 1];
    }
    head_kernel<<<nblk, 512, HEAD_SMEM_FLOATS * 4>>>(xin, lin2_W, lin2_b, (float*)d_out);
}

// round 7
// speedup vs baseline: 1.3752x; 1.3752x over previous
#include <cuda_runtime.h>
#include <mma.h>
#include <cstdint>

using namespace nvcuda;

#define NNODES 50000
#define NEDGES 800000
#define FDIM 64
#define NCLS 40
#define NLAYER 3

// ---------------- device scratch (no allocations allowed) ----------------
__device__ __align__(16) float g_agg[NNODES * FDIM];
__device__ __align__(16) float g_xA[NNODES * FDIM];
__device__ __align__(16) float g_xB[NNODES * FDIM];
__device__ __align__(16) float g_W1f[NLAYER * FDIM * 128];   // 3 x 64 x 128
__device__ __align__(16) float g_b1f[NLAYER * 128];
__device__ __align__(16) float g_W2f[NLAYER * 128 * FDIM];   // 3 x 128 x 64
__device__ __align__(16) float g_b2f[NLAYER * FDIM];
__device__ __align__(16) float g_lin1f[FDIM * FDIM];
__device__ __align__(16) float g_b1hf[FDIM];

// ---------------- BN folding ----------------
__global__ void prep_kernel(
    const float* __restrict__ W1s, const float* __restrict__ b1s,
    const float* __restrict__ g1s, const float* __restrict__ bt1s,
    const float* __restrict__ m1s, const float* __restrict__ v1s,
    const float* __restrict__ W2s, const float* __restrict__ b2s,
    const float* __restrict__ gcs, const float* __restrict__ bcs,
    const float* __restrict__ mcs, const float* __restrict__ vcs,
    const float* __restrict__ lin1_W, const float* __restrict__ lin1_b,
    const float* __restrict__ g_bn1, const float* __restrict__ b_bn1,
    const float* __restrict__ m_bn1, const float* __restrict__ v_bn1)
{
    const float eps = 1e-5f;
    int t = blockIdx.x * blockDim.x + threadIdx.x;
    if (t < NLAYER * FDIM * 128) {                     // W1f: 24576
        int l = t / (FDIM * 128);
        int rem = t % (FDIM * 128);
        int j = rem % 128;
        float a = g1s[l * 128 + j] * rsqrtf(v1s[l * 128 + j] + eps);
        g_W1f[t] = W1s[t] * a;
        if (rem < 128)
            g_b1f[l * 128 + rem] =
                (b1s[l * 128 + rem] - m1s[l * 128 + rem]) * a + bt1s[l * 128 + rem];
    } else if (t < 24576 + NLAYER * 128 * FDIM) {      // W2f: 24576
        int u = t - 24576;
        int l = u / (128 * FDIM);
        int rem = u % (128 * FDIM);
        int j = rem % FDIM;
        float a = gcs[l * FDIM + j] * rsqrtf(vcs[l * FDIM + j] + eps);
        g_W2f[u] = W2s[u] * a;
        if (rem < FDIM)
            g_b2f[l * FDIM + rem] =
                (b2s[l * FDIM + rem] - mcs[l * FDIM + rem]) * a + bcs[l * FDIM + rem];
    } else if (t < 49152 + FDIM * FDIM) {              // lin1f: 4096
        int u = t - 49152;
        int j = u % FDIM;
        float a = g_bn1[j] * rsqrtf(v_bn1[j] + eps);
        g_lin1f[u] = lin1_W[u] * a;
        if (u < FDIM)
            g_b1hf[u] = (lin1_b[u] - m_bn1[u]) * a + b_bn1[u];
    }
}

// ---------------- edge scatter: agg[dst] += x[src] (agg preinit to x) ----------------
__global__ void scatter_kernel(const int* __restrict__ ei,
                               const float* __restrict__ x)
{
    int t = blockIdx.x * blockDim.x + threadIdx.x;
    if (t >= NEDGES * 16) return;
    int e = t >> 4;
    int q = t & 15;
    int s = __ldg(&ei[e]);
    int d = __ldg(&ei[NEDGES + e]);
    if ((unsigned)s >= NNODES || (unsigned)d >= NNODES) return;
    float4 v = __ldg((const float4*)x + (size_t)s * 16 + q);
    float* p = g_agg + (size_t)d * FDIM + q * 4;
    asm volatile("red.global.add.v4.f32 [%0], {%1,%2,%3,%4};"
                 :: "l"(p), "f"(v.x), "f"(v.y), "f"(v.z), "f"(v.w)
                 : "memory");
}

// ---------------- fused GIN MLP on tf32 tensor cores ----------------
// 128 nodes per CTA, 256 threads (8 warps).
// smem strides padded to multiple-of-8 floats.
#define SH_LD  72     // H: 128 x 72
#define ST_LD  136    // T: 128 x 136
#define SW1_LD 136    // W1: 64 x 136  (k-major rows)
#define SW2_LD 72     // W2: 128 x 72
#define MLP_W_FLOATS (128*SH_LD + 128*ST_LD + 64*SW1_LD + 128*SW2_LD + 128 + 64)

__global__ __launch_bounds__(256, 1)
void mlp_wmma_kernel(const float* __restrict__ W1f, const float* __restrict__ b1f,
                     const float* __restrict__ W2f, const float* __restrict__ b2f,
                     float* __restrict__ xout)
{
    extern __shared__ float smem[];
    float* sH  = smem;                    // 128 x 72
    float* sT  = sH  + 128 * SH_LD;       // 128 x 136
    float* sW1 = sT  + 128 * ST_LD;       // 64 x 136
    float* sW2 = sW1 + 64 * SW1_LD;       // 128 x 72
    float* sB1 = sW2 + 128 * SW2_LD;      // 128
    float* sB2 = sB1 + 128;               // 64

    const int tid = threadIdx.x;          // 256
    const int wid = tid >> 5;             // 0..7
    const int node0 = blockIdx.x * 128;

    // loads
    for (int i = tid; i < 64 * 128; i += 256) {       // W1 [64k x 128n]
        int k = i >> 7, n = i & 127;
        sW1[k * SW1_LD + n] = W1f[i];
    }
    for (int i = tid; i < 128 * 64; i += 256) {       // W2 [128k x 64n]
        int k = i >> 6, n = i & 63;
        sW2[k * SW2_LD + n] = W2f[i];
    }
    if (tid < 128) sB1[tid] = b1f[tid];
    else if (tid < 192) sB2[tid - 128] = b2f[tid - 128];
    for (int i = tid; i < 128 * 64; i += 256) {       // H tile
        int r = i >> 6, c = i & 63;
        int node = node0 + r;
        sH[r * SH_LD + c] = (node < NNODES) ? g_agg[(size_t)node * FDIM + c] : 0.f;
    }
    __syncthreads();

    // ---- stage 1: T[128x128] = H[128x64] @ W1[64x128] ----
    {
        wmma::fragment<wmma::accumulator, 16, 16, 8, float> acc[8];
        #pragma unroll
        for (int n0 = 0; n0 < 8; n0++) wmma::fill_fragment(acc[n0], 0.f);

        #pragma unroll
        for (int k0 = 0; k0 < 8; k0++) {
            wmma::fragment<wmma::matrix_a, 16, 16, 8, wmma::precision::tf32, wmma::row_major> a;
            wmma::load_matrix_sync(a, sH + wid * 16 * SH_LD + k0 * 8, SH_LD);
            #pragma unroll
            for (int i = 0; i < a.num_elements; i++) a.x[i] = wmma::__float_to_tf32(a.x[i]);
            #pragma unroll
            for (int n0 = 0; n0 < 8; n0++) {
                wmma::fragment<wmma::matrix_b, 16, 16, 8, wmma::precision::tf32, wmma::row_major> b;
                wmma::load_matrix_sync(b, sW1 + k0 * 8 * SW1_LD + n0 * 16, SW1_LD);
                #pragma unroll
                for (int i = 0; i < b.num_elements; i++) b.x[i] = wmma::__float_to_tf32(b.x[i]);
                wmma::mma_sync(acc[n0], a, b, acc[n0]);
            }
        }
        #pragma unroll
        for (int n0 = 0; n0 < 8; n0++)
            wmma::store_matrix_sync(sT + wid * 16 * ST_LD + n0 * 16, acc[n0], ST_LD,
                                    wmma::mem_row_major);
    }
    __syncthreads();

    // bias + relu on T
    for (int i = tid; i < 128 * 128; i += 256) {
        int r = i >> 7, c = i & 127;
        float v = sT[r * ST_LD + c] + sB1[c];
        sT[r * ST_LD + c] = fmaxf(v, 0.f);
    }
    __syncthreads();

    // ---- stage 2: O[128x64] = T[128x128] @ W2[128x64] ----
    {
        wmma::fragment<wmma::accumulator, 16, 16, 8, float> acc[4];
        #pragma unroll
        for (int n0 = 0; n0 < 4; n0++) wmma::fill_fragment(acc[n0], 0.f);

        #pragma unroll
        for (int k0 = 0; k0 < 16; k0++) {
            wmma::fragment<wmma::matrix_a, 16, 16, 8, wmma::precision::tf32, wmma::row_major> a;
            wmma::load_matrix_sync(a, sT + wid * 16 * ST_LD + k0 * 8, ST_LD);
            #pragma unroll
            for (int i = 0; i < a.num_elements; i++) a.x[i] = wmma::__float_to_tf32(a.x[i]);
            #pragma unroll
            for (int n0 = 0; n0 < 4; n0++) {
                wmma::fragment<wmma::matrix_b, 16, 16, 8, wmma::precision::tf32, wmma::row_major> b;
                wmma::load_matrix_sync(b, sW2 + k0 * 8 * SW2_LD + n0 * 16, SW2_LD);
                #pragma unroll
                for (int i = 0; i < b.num_elements; i++) b.x[i] = wmma::__float_to_tf32(b.x[i]);
                wmma::mma_sync(acc[n0], a, b, acc[n0]);
            }
        }
        // reuse sH as output staging (128 x 72)
        #pragma unroll
        for (int n0 = 0; n0 < 4; n0++)
            wmma::store_matrix_sync(sH + wid * 16 * SH_LD + n0 * 16, acc[n0], SH_LD,
                                    wmma::mem_row_major);
    }
    __syncthreads();

    // bias + relu + writeout
    for (int i = tid; i < 128 * 64; i += 256) {
        int r = i >> 6, c = i & 63;
        int node = node0 + r;
        if (node < NNODES)
            xout[(size_t)node * FDIM + c] = fmaxf(sH[r * SH_LD + c] + sB2[c], 0.f);
    }
}

// ---------------- head: relu(bn1(lin1 @ x)) -> lin2 -> log_softmax ----------------
#define HEAD_SMEM_FLOATS (4096 + 2560 + 4096 + 4096 + 2560 + 64 + 40 + 64 + 64)
__global__ void head_kernel(const float* __restrict__ xin,
                            const float* __restrict__ lin2_W,
                            const float* __restrict__ lin2_b,
                            float* __restrict__ out)
{
    extern __shared__ float smem[];
    float* sW1  = smem;            // 64x64 folded lin1
    float* sW2  = sW1 + 4096;      // 64x40
    float* sh   = sW2 + 2560;      // 64x64 input tile
    float* sh1  = sh + 4096;       // 64x64 hidden
    float* slog = sh1 + 4096;      // 64x40 logits
    float* sB1  = slog + 2560;     // 64
    float* sB2  = sB1 + 64;        // 40
    float* rmax = sB2 + 40;        // 64
    float* rlse = rmax + 64;       // 64

    int tid = threadIdx.x;         // 512
    int node0 = blockIdx.x * 64;

    for (int i = tid; i < 4096; i += 512) sW1[i] = g_lin1f[i];
    for (int i = tid; i < 2560; i += 512) sW2[i] = lin2_W[i];
    if (tid < 64) sB1[tid] = g_b1hf[tid];
    else if (tid < 104) sB2[tid - 64] = lin2_b[tid - 64];
    for (int i = tid; i < 4096; i += 512) {
        int node = node0 + (i >> 6);
        sh[i] = (node < NNODES) ? xin[(size_t)node * FDIM + (i & 63)] : 0.f;
    }
    __syncthreads();

    // stage 1: h1 = relu(x @ lin1f + b); 2 rows x 4 cols per thread
    {
        int rb = (tid >> 4) * 2;
        int cb = (tid & 15) * 4;
        float acc[2][4];
        #pragma unroll
        for (int i = 0; i < 2; i++)
            #pragma unroll
            for (int j = 0; j < 4; j++) acc[i][j] = sB1[cb + j];
        #pragma unroll 4
        for (int k = 0; k < 64; k++) {
            float w[4];
            #pragma unroll
            for (int j = 0; j < 4; j++) w[j] = sW1[k * 64 + cb + j];
            #pragma unroll
            for (int i = 0; i < 2; i++) {
                float hv = sh[(rb + i) * 64 + k];
                #pragma unroll
                for (int j = 0; j < 4; j++) acc[i][j] = fmaf(hv, w[j], acc[i][j]);
            }
        }
        #pragma unroll
        for (int i = 0; i < 2; i++)
            #pragma unroll
            for (int j = 0; j < 4; j++)
                sh1[(rb + i) * 64 + cb + j] = fmaxf(acc[i][j], 0.f);
    }
    __syncthreads();

    // stage 2: logits = h1 @ lin2 + b; 1 row x 5 cols per thread
    {
        int r = tid >> 3;
        int c0 = (tid & 7) * 5;
        float acc[5];
        #pragma unroll
        for (int j = 0; j < 5; j++) acc[j] = sB2[c0 + j];
        #pragma unroll 4
        for (int k = 0; k < 64; k++) {
            float hv = sh1[r * 64 + k];
            #pragma unroll
            for (int j = 0; j < 5; j++) acc[j] = fmaf(hv, sW2[k * 40 + c0 + j], acc[j]);
        }
        #pragma unroll
        for (int j = 0; j < 5; j++) slog[r * 40 + c0 + j] = acc[j];
    }
    __syncthreads();

    // row stats
    if (tid < 64) {
        float m = -3.4e38f;
        #pragma unroll 8
        for (int c = 0; c < NCLS; c++) m = fmaxf(m, slog[tid * 40 + c]);
        float s = 0.f;
        #pragma unroll 8
        for (int c = 0; c < NCLS; c++) s += expf(slog[tid * 40 + c] - m);
        rmax[tid] = m;
        rlse[tid] = logf(s);
    }
    __syncthreads();

    for (int i = tid; i < 64 * NCLS; i += 512) {
        int r = i / NCLS;
        int node = node0 + r;
        if (node < NNODES)
            out[(size_t)node * NCLS + (i % NCLS)] = slog[i] - rmax[r] - rlse[r];
    }
}

// ---------------- launcher ----------------
extern "C" void kernel_launch(void* const* d_in, const int* in_sizes, int n_in,
                              void* d_out, int out_size)
{
    const float* x     = (const float*)d_in[0];
    const int*   ei    = (const int*)d_in[1];
    const float* W1s   = (const float*)d_in[2];
    const float* b1s   = (const float*)d_in[3];
    const float* g1s   = (const float*)d_in[4];
    const float* bt1s  = (const float*)d_in[5];
    const float* m1s   = (const float*)d_in[6];
    const float* v1s   = (const float*)d_in[7];
    const float* W2s   = (const float*)d_in[8];
    const float* b2s   = (const float*)d_in[9];
    const float* gcs   = (const float*)d_in[10];
    const float* bcs   = (const float*)d_in[11];
    const float* mcs   = (const float*)d_in[12];
    const float* vcs   = (const float*)d_in[13];
    const float* lin1_W = (const float*)d_in[14];
    const float* lin1_b = (const float*)d_in[15];
    const float* g_bn1 = (const float*)d_in[16];
    const float* b_bn1 = (const float*)d_in[17];
    const float* m_bn1 = (const float*)d_in[18];
    const float* v_bn1 = (const float*)d_in[19];
    const float* lin2_W = (const float*)d_in[20];
    const float* lin2_b = (const float*)d_in[21];

    float *aggp, *xAp, *xBp, *W1fp, *b1fp, *W2fp, *b2fp;
    cudaGetSymbolAddress((void**)&aggp, g_agg);
    cudaGetSymbolAddress((void**)&xAp,  g_xA);
    cudaGetSymbolAddress((void**)&xBp,  g_xB);
    cudaGetSymbolAddress((void**)&W1fp, g_W1f);
    cudaGetSymbolAddress((void**)&b1fp, g_b1f);
    cudaGetSymbolAddress((void**)&W2fp, g_W2f);
    cudaGetSymbolAddress((void**)&b2fp, g_b2f);

    cudaFuncSetAttribute(mlp_wmma_kernel, cudaFuncAttributeMaxDynamicSharedMemorySize,
                         MLP_W_FLOATS * 4);
    cudaFuncSetAttribute(head_kernel, cudaFuncAttributeMaxDynamicSharedMemorySize,
                         HEAD_SMEM_FLOATS * 4);

    prep_kernel<<<(53280 + 255) / 256, 256>>>(W1s, b1s, g1s, bt1s, m1s, v1s,
                                              W2s, b2s, gcs, bcs, mcs, vcs,
                                              lin1_W, lin1_b, g_bn1, b_bn1, m_bn1, v_bn1);

    const int nblk128 = (NNODES + 127) / 128;
    const int nblk64  = (NNODES + 63) / 64;
    const float* xin = x;
    float* bufs[2] = { xAp, xBp };
    for (int l = 0; l < NLAYER; l++) {
        cudaMemcpyAsync(aggp, xin, (size_t)NNODES * FDIM * sizeof(float),
                        cudaMemcpyDeviceToDevice);
        scatter_kernel<<<(NEDGES * 16 + 255) / 256, 256>>>(ei, xin);
        mlp_wmma_kernel<<<nblk128, 256, MLP_W_FLOATS * 4>>>(
            W1fp + l * 8192, b1fp + l * 128, W2fp + l * 8192, b2fp + l * 64,
            bufs[l & 1]);
        xin = bufs[l & 1];
    }
    head_kernel<<<nblk64, 512, HEAD_SMEM_FLOATS * 4>>>(xin, lin2_W, lin2_b, (float*)d_out);
}

// round 13
// speedup vs baseline: 1.3936x; 1.0134x over previous
#include <cuda_runtime.h>
#include <cuda_bf16.h>
#include <mma.h>
#include <cstdint>

using namespace nvcuda;

#define NNODES 50000
#define NEDGES 800000
#define FDIM 64
#define NCLS 40
#define NLAYER 3

// ---------------- device scratch (no allocations allowed) ----------------
__device__ __align__(16) float g_agg[NNODES * FDIM];
__device__ __align__(16) float g_xA[NNODES * FDIM];
__device__ __align__(16) float g_xB[NNODES * FDIM];
__device__ __align__(16) __nv_bfloat16 g_W1h[NLAYER * FDIM * 128];  // 3 x 64k x 128n
__device__ __align__(16) __nv_bfloat16 g_W2h[NLAYER * 128 * FDIM];  // 3 x 128k x 64n
__device__ __align__(16) float g_b1f[NLAYER * 128];
__device__ __align__(16) float g_b2f[NLAYER * FDIM];
__device__ __align__(16) float g_lin1f[FDIM * FDIM];
__device__ __align__(16) float g_b1hf[FDIM];

// ---------------- BN folding (weights -> bf16) ----------------
__global__ void prep_kernel(
    const float* __restrict__ W1s, const float* __restrict__ b1s,
    const float* __restrict__ g1s, const float* __restrict__ bt1s,
    const float* __restrict__ m1s, const float* __restrict__ v1s,
    const float* __restrict__ W2s, const float* __restrict__ b2s,
    const float* __restrict__ gcs, const float* __restrict__ bcs,
    const float* __restrict__ mcs, const float* __restrict__ vcs,
    const float* __restrict__ lin1_W, const float* __restrict__ lin1_b,
    const float* __restrict__ g_bn1, const float* __restrict__ b_bn1,
    const float* __restrict__ m_bn1, const float* __restrict__ v_bn1)
{
    const float eps = 1e-5f;
    int t = blockIdx.x * blockDim.x + threadIdx.x;
    if (t < NLAYER * FDIM * 128) {                     // W1: 24576
        int l = t / (FDIM * 128);
        int rem = t % (FDIM * 128);
        int j = rem % 128;
        float a = g1s[l * 128 + j] * rsqrtf(v1s[l * 128 + j] + eps);
        g_W1h[t] = __float2bfloat16(W1s[t] * a);
        if (rem < 128)
            g_b1f[l * 128 + rem] =
                (b1s[l * 128 + rem] - m1s[l * 128 + rem]) * a + bt1s[l * 128 + rem];
    } else if (t < 24576 + NLAYER * 128 * FDIM) {      // W2: 24576
        int u = t - 24576;
        int l = u / (128 * FDIM);
        int rem = u % (128 * FDIM);
        int j = rem % FDIM;
        float a = gcs[l * FDIM + j] * rsqrtf(vcs[l * FDIM + j] + eps);
        g_W2h[u] = __float2bfloat16(W2s[u] * a);
        if (rem < FDIM)
            g_b2f[l * FDIM + rem] =
                (b2s[l * FDIM + rem] - mcs[l * FDIM + rem]) * a + bcs[l * FDIM + rem];
    } else if (t < 49152 + FDIM * FDIM) {              // lin1f: 4096
        int u = t - 49152;
        int j = u % FDIM;
        float a = g_bn1[j] * rsqrtf(v_bn1[j] + eps);
        g_lin1f[u] = lin1_W[u] * a;
        if (u < FDIM)
            g_b1hf[u] = (lin1_b[u] - m_bn1[u]) * a + b_bn1[u];
    }
}

// ---------------- edge scatter: g_agg[dst] += x[src] (agg pre-zeroed) ----------------
__global__ void scatter_kernel(const int* __restrict__ ei,
                               const float* __restrict__ x)
{
    int t = blockIdx.x * blockDim.x + threadIdx.x;
    if (t >= (NEDGES / 4) * 16) return;
    int g = t >> 4;
    int q = t & 15;
    int4 ss = __ldg((const int4*)ei + g);
    int4 dd = __ldg((const int4*)(ei + NEDGES) + g);
    int s[4] = { ss.x, ss.y, ss.z, ss.w };
    int d[4] = { dd.x, dd.y, dd.z, dd.w };
    float4 v[4];
    #pragma unroll
    for (int i = 0; i < 4; i++) {
        bool ok = (unsigned)s[i] < NNODES;
        v[i] = ok ? __ldg((const float4*)x + (size_t)s[i] * 16 + q)
                  : make_float4(0.f, 0.f, 0.f, 0.f);
    }
    #pragma unroll
    for (int i = 0; i < 4; i++) {
        if ((unsigned)d[i] < NNODES && (unsigned)s[i] < NNODES) {
            float* p = g_agg + (size_t)d[i] * FDIM + q * 4;
            asm volatile("red.global.add.v4.f32 [%0], {%1,%2,%3,%4};"
                         :: "l"(p), "f"(v[i].x), "f"(v[i].y), "f"(v[i].z), "f"(v[i].w)
                         : "memory");
        }
    }
}

// ---------------- fused GIN MLP on bf16 tensor cores ----------------
// 128 nodes/CTA, 256 threads (8 warps, 16 rows each). h = agg + x computed here;
// agg tile rewritten to zero for next layer's scatter.
#define SH_LD  80     // bf16: 128 x 80
#define ST_LD  144    // bf16: 128 x 144
#define SW1_LD 144    // bf16: 64 x 144
#define SW2_LD 80     // bf16: 128 x 80
#define SSTG_LD 20    // fp32 staging ld: MUST be multiple of 4 for wmma store
#define MLP_BF16_ELEMS (128*SH_LD + 128*ST_LD + 64*SW1_LD + 128*SW2_LD)   // 48128
#define MLP_SMEM_BYTES (MLP_BF16_ELEMS*2 + 8*16*SSTG_LD*4 + 128*4 + 64*4) // 107264

__global__ __launch_bounds__(256, 2)
void mlp_wmma_kernel(const float* __restrict__ xin,
                     const __nv_bfloat16* __restrict__ W1h, const float* __restrict__ b1f,
                     const __nv_bfloat16* __restrict__ W2h, const float* __restrict__ b2f,
                     float* __restrict__ xout)
{
    extern __shared__ __align__(16) unsigned char smem_raw[];
    __nv_bfloat16* sH  = (__nv_bfloat16*)smem_raw;              // 128 x 80
    __nv_bfloat16* sT  = sH + 128 * SH_LD;                      // 128 x 144
    __nv_bfloat16* sW1 = sT + 128 * ST_LD;                      // 64 x 144
    __nv_bfloat16* sW2 = sW1 + 64 * SW1_LD;                     // 128 x 80
    float* sS  = (float*)(smem_raw + MLP_BF16_ELEMS * 2);       // 8 x 16 x 20 staging
    float* sB1 = sS + 8 * 16 * SSTG_LD;                         // 128
    float* sB2 = sB1 + 128;                                     // 64

    const int tid  = threadIdx.x;        // 256
    const int wid  = tid >> 5;           // 0..7
    const int lane = tid & 31;
    const int node0 = blockIdx.x * 128;

    // weights -> smem (vectorized 4x bf16)
    for (int i = tid; i < 64 * 32; i += 256) {         // W1: 64 x 128
        int k = i >> 5, n4 = (i & 31) * 4;
        uint2 w = *(const uint2*)(W1h + k * 128 + n4);
        *(uint2*)(sW1 + k * SW1_LD + n4) = w;
    }
    for (int i = tid; i < 128 * 16; i += 256) {        // W2: 128 x 64
        int k = i >> 4, n4 = (i & 15) * 4;
        uint2 w = *(const uint2*)(W2h + k * 64 + n4);
        *(uint2*)(sW2 + k * SW2_LD + n4) = w;
    }
    if (tid < 128) sB1[tid] = b1f[tid];
    else if (tid < 192) sB2[tid - 128] = b2f[tid - 128];

    // H = agg + x (fp32 -> bf16), and zero agg tile for next layer
    for (int i = tid; i < 128 * 16; i += 256) {
        int r = i >> 4, c4 = (i & 15) * 4;
        int node = node0 + r;
        float4 h = make_float4(0.f, 0.f, 0.f, 0.f);
        if (node < NNODES) {
            float4 a  = *(const float4*)(g_agg + (size_t)node * FDIM + c4);
            float4 xv = *(const float4*)(xin   + (size_t)node * FDIM + c4);
            h = make_float4(a.x + xv.x, a.y + xv.y, a.z + xv.z, a.w + xv.w);
            *(float4*)(g_agg + (size_t)node * FDIM + c4) = make_float4(0.f, 0.f, 0.f, 0.f);
        }
        __nv_bfloat162 p0 = __floats2bfloat162_rn(h.x, h.y);
        __nv_bfloat162 p1 = __floats2bfloat162_rn(h.z, h.w);
        *(uint32_t*)(sH + r * SH_LD + c4)     = *(uint32_t*)&p0;
        *(uint32_t*)(sH + r * SH_LD + c4 + 2) = *(uint32_t*)&p1;
    }
    __syncthreads();

    float* sSw = sS + wid * 16 * SSTG_LD;   // warp-private 16x20 staging

    // ---- stage 1: T[128x128] = relu(H[128x64] @ W1 + b1), warp-local rows ----
    {
        wmma::fragment<wmma::accumulator, 16, 16, 16, float> acc[8];
        #pragma unroll
        for (int n0 = 0; n0 < 8; n0++) wmma::fill_fragment(acc[n0], 0.f);

        #pragma unroll
        for (int k0 = 0; k0 < 4; k0++) {
            wmma::fragment<wmma::matrix_a, 16, 16, 16, __nv_bfloat16, wmma::row_major> a;
            wmma::load_matrix_sync(a, sH + wid * 16 * SH_LD + k0 * 16, SH_LD);
            #pragma unroll
            for (int n0 = 0; n0 < 8; n0++) {
                wmma::fragment<wmma::matrix_b, 16, 16, 16, __nv_bfloat16, wmma::row_major> b;
                wmma::load_matrix_sync(b, sW1 + k0 * 16 * SW1_LD + n0 * 16, SW1_LD);
                wmma::mma_sync(acc[n0], a, b, acc[n0]);
            }
        }
        #pragma unroll
        for (int n0 = 0; n0 < 8; n0++) {
            wmma::store_matrix_sync(sSw, acc[n0], SSTG_LD, wmma::mem_row_major);
            __syncwarp();
            #pragma unroll
            for (int i = 0; i < 8; i++) {
                int idx = i * 32 + lane;
                int r = idx >> 4, c = idx & 15;
                float v = sSw[r * SSTG_LD + c] + sB1[n0 * 16 + c];
                sT[(wid * 16 + r) * ST_LD + n0 * 16 + c] =
                    __float2bfloat16(fmaxf(v, 0.f));
            }
            __syncwarp();
        }
    }
    // no block sync needed: each warp consumes only its own T rows

    // ---- stage 2: O[128x64] = relu(T[128x128] @ W2 + b2) ----
    {
        wmma::fragment<wmma::accumulator, 16, 16, 16, float> acc[4];
        #pragma unroll
        for (int n0 = 0; n0 < 4; n0++) wmma::fill_fragment(acc[n0], 0.f);

        #pragma unroll
        for (int k0 = 0; k0 < 8; k0++) {
            wmma::fragment<wmma::matrix_a, 16, 16, 16, __nv_bfloat16, wmma::row_major> a;
            wmma::load_matrix_sync(a, sT + wid * 16 * ST_LD + k0 * 16, ST_LD);
            #pragma unroll
            for (int n0 = 0; n0 < 4; n0++) {
                wmma::fragment<wmma::matrix_b, 16, 16, 16, __nv_bfloat16, wmma::row_major> b;
                wmma::load_matrix_sync(b, sW2 + k0 * 16 * SW2_LD + n0 * 16, SW2_LD);
                wmma::mma_sync(acc[n0], a, b, acc[n0]);
            }
        }
        #pragma unroll
        for (int n0 = 0; n0 < 4; n0++) {
            wmma::store_matrix_sync(sSw, acc[n0], SSTG_LD, wmma::mem_row_major);
            __syncwarp();
            #pragma unroll
            for (int i = 0; i < 8; i++) {
                int idx = i * 32 + lane;
                int r = idx >> 4, c = idx & 15;
                int node = node0 + wid * 16 + r;
                if (node < NNODES) {
                    float v = sSw[r * SSTG_LD + c] + sB2[n0 * 16 + c];
                    xout[(size_t)node * FDIM + n0 * 16 + c] = fmaxf(v, 0.f);
                }
            }
            __syncwarp();
        }
    }
}

// ---------------- head: relu(bn1(lin1 @ x)) -> lin2 -> log_softmax ----------------
#define HEAD_SMEM_FLOATS (4096 + 2560 + 4096 + 4096 + 2560 + 64 + 40 + 64 + 64)
__global__ void head_kernel(const float* __restrict__ xin,
                            const float* __restrict__ lin2_W,
                            const float* __restrict__ lin2_b,
                            float* __restrict__ out)
{
    extern __shared__ float smem[];
    float* sW1  = smem;            // 64x64 folded lin1
    float* sW2  = sW1 + 4096;      // 64x40
    float* sh   = sW2 + 2560;      // 64x64 input tile
    float* sh1  = sh + 4096;       // 64x64 hidden
    float* slog = sh1 + 4096;      // 64x40 logits
    float* sB1  = slog + 2560;     // 64
    float* sB2  = sB1 + 64;        // 40
    float* rmax = sB2 + 40;        // 64
    float* rlse = rmax + 64;       // 64

    int tid = threadIdx.x;         // 512
    int node0 = blockIdx.x * 64;

    for (int i = tid; i < 4096; i += 512) sW1[i] = g_lin1f[i];
    for (int i = tid; i < 2560; i += 512) sW2[i] = lin2_W[i];
    if (tid < 64) sB1[tid] = g_b1hf[tid];
    else if (tid < 104) sB2[tid - 64] = lin2_b[tid - 64];
    for (int i = tid; i < 4096; i += 512) {
        int node = node0 + (i >> 6);
        sh[i] = (node < NNODES) ? xin[(size_t)node * FDIM + (i & 63)] : 0.f;
    }
    __syncthreads();

    {
        int rb = (tid >> 4) * 2;
        int cb = (tid & 15) * 4;
        float acc[2][4];
        #pragma unroll
        for (int i = 0; i < 2; i++)
            #pragma unroll
            for (int j = 0; j < 4; j++) acc[i][j] = sB1[cb + j];
        #pragma unroll 4
        for (int k = 0; k < 64; k++) {
            float w[4];
            #pragma unroll
            for (int j = 0; j < 4; j++) w[j] = sW1[k * 64 + cb + j];
            #pragma unroll
            for (int i = 0; i < 2; i++) {
                float hv = sh[(rb + i) * 64 + k];
                #pragma unroll
                for (int j = 0; j < 4; j++) acc[i][j] = fmaf(hv, w[j], acc[i][j]);
            }
        }
        #pragma unroll
        for (int i = 0; i < 2; i++)
            #pragma unroll
            for (int j = 0; j < 4; j++)
                sh1[(rb + i) * 64 + cb + j] = fmaxf(acc[i][j], 0.f);
    }
    __syncthreads();

    {
        int r = tid >> 3;
        int c0 = (tid & 7) * 5;
        float acc[5];
        #pragma unroll
        for (int j = 0; j < 5; j++) acc[j] = sB2[c0 + j];
        #pragma unroll 4
        for (int k = 0; k < 64; k++) {
            float hv = sh1[r * 64 + k];
            #pragma unroll
            for (int j = 0; j < 5; j++) acc[j] = fmaf(hv, sW2[k * 40 + c0 + j], acc[j]);
        }
        #pragma unroll
        for (int j = 0; j < 5; j++) slog[r * 40 + c0 + j] = acc[j];
    }
    __syncthreads();

    if (tid < 64) {
        float m = -3.4e38f;
        #pragma unroll 8
        for (int c = 0; c < NCLS; c++) m = fmaxf(m, slog[tid * 40 + c]);
        float s = 0.f;
        #pragma unroll 8
        for (int c = 0; c < NCLS; c++) s += expf(slog[tid * 40 + c] - m);
        rmax[tid] = m;
        rlse[tid] = logf(s);
    }
    __syncthreads();

    for (int i = tid; i < 64 * NCLS; i += 512) {
        int r = i / NCLS;
        int node = node0 + r;
        if (node < NNODES)
            out[(size_t)node * NCLS + (i % NCLS)] = slog[i] - rmax[r] - rlse[r];
    }
}

// ---------------- launcher ----------------
extern "C" void kernel_launch(void* const* d_in, const int* in_sizes, int n_in,
                              void* d_out, int out_size)
{
    const float* x     = (const float*)d_in[0];
    const int*   ei    = (const int*)d_in[1];
    const float* W1s   = (const float*)d_in[2];
    const float* b1s   = (const float*)d_in[3];
    const float* g1s   = (const float*)d_in[4];
    const float* bt1s  = (const float*)d_in[5];
    const float* m1s   = (const float*)d_in[6];
    const float* v1s   = (const float*)d_in[7];
    const float* W2s   = (const float*)d_in[8];
    const float* b2s   = (const float*)d_in[9];
    const float* gcs   = (const float*)d_in[10];
    const float* bcs   = (const float*)d_in[11];
    const float* mcs   = (const float*)d_in[12];
    const float* vcs   = (const float*)d_in[13];
    const float* lin1_W = (const float*)d_in[14];
    const float* lin1_b = (const float*)d_in[15];
    const float* g_bn1 = (const float*)d_in[16];
    const float* b_bn1 = (const float*)d_in[17];
    const float* m_bn1 = (const float*)d_in[18];
    const float* v_bn1 = (const float*)d_in[19];
    const float* lin2_W = (const float*)d_in[20];
    const float* lin2_b = (const float*)d_in[21];

    float *aggp, *xAp, *xBp, *b1fp, *b2fp;
    __nv_bfloat16 *W1hp, *W2hp;
    cudaGetSymbolAddress((void**)&aggp, g_agg);
    cudaGetSymbolAddress((void**)&xAp,  g_xA);
    cudaGetSymbolAddress((void**)&xBp,  g_xB);
    cudaGetSymbolAddress((void**)&W1hp, g_W1h);
    cudaGetSymbolAddress((void**)&W2hp, g_W2h);
    cudaGetSymbolAddress((void**)&b1fp, g_b1f);
    cudaGetSymbolAddress((void**)&b2fp, g_b2f);

    cudaFuncSetAttribute(mlp_wmma_kernel, cudaFuncAttributeMaxDynamicSharedMemorySize,
                         MLP_SMEM_BYTES);
    cudaFuncSetAttribute(head_kernel, cudaFuncAttributeMaxDynamicSharedMemorySize,
                         HEAD_SMEM_FLOATS * 4);

    cudaMemsetAsync(aggp, 0, (size_t)NNODES * FDIM * sizeof(float));
    prep_kernel<<<(53280 + 255) / 256, 256>>>(W1s, b1s, g1s, bt1s, m1s, v1s,
                                              W2s, b2s, gcs, bcs, mcs, vcs,
                                              lin1_W, lin1_b, g_bn1, b_bn1, m_bn1, v_bn1);

    const int nblk128 = (NNODES + 127) / 128;
    const int nblk64  = (NNODES + 63) / 64;
    const int scatter_threads = (NEDGES / 4) * 16;
    const float* xin = x;
    float* bufs[2] = { xAp, xBp };
    for (int l = 0; l < NLAYER; l++) {
        scatter_kernel<<<(scatter_threads + 255) / 256, 256>>>(ei, xin);
        mlp_wmma_kernel<<<nblk128, 256, MLP_SMEM_BYTES>>>(
            xin, W1hp + l * 8192, b1fp + l * 128, W2hp + l * 8192, b2fp + l * 64,
            bufs[l & 1]);
        xin = bufs[l & 1];
    }
    head_kernel<<<nblk64, 512, HEAD_SMEM_FLOATS * 4>>>(xin, lin2_W, lin2_b, (float*)d_out);
}

// round 14
// speedup vs baseline: 1.5401x; 1.1051x over previous
#include <cuda_runtime.h>
#include <cuda_bf16.h>
#include <cstdint>

#define NNODES 50000
#define NEDGES 800000
#define FDIM 64
#define NCLS 40
#define NLAYER 3

// ---------------- device scratch (no allocations allowed) ----------------
__device__ __align__(16) float g_agg[NNODES * FDIM];
__device__ __align__(16) float g_xA[NNODES * FDIM];
__device__ __align__(16) float g_xB[NNODES * FDIM];
__device__ __align__(16) __nv_bfloat16 g_W1h[NLAYER * FDIM * 128];  // 3 x 64k x 128n
__device__ __align__(16) __nv_bfloat16 g_W2h[NLAYER * 128 * FDIM];  // 3 x 128k x 64n
__device__ __align__(16) float g_b1f[NLAYER * 128];
__device__ __align__(16) float g_b2f[NLAYER * FDIM];
__device__ __align__(16) float g_lin1f[FDIM * FDIM];
__device__ __align__(16) float g_b1hf[FDIM];

// ---------------- BN folding (weights -> bf16) + agg zeroing ----------------
#define PREP_FOLD 53280
#define PREP_ZERO 800000   // 3.2M floats as float4
__global__ void prep_kernel(
    const float* __restrict__ W1s, const float* __restrict__ b1s,
    const float* __restrict__ g1s, const float* __restrict__ bt1s,
    const float* __restrict__ m1s, const float* __restrict__ v1s,
    const float* __restrict__ W2s, const float* __restrict__ b2s,
    const float* __restrict__ gcs, const float* __restrict__ bcs,
    const float* __restrict__ mcs, const float* __restrict__ vcs,
    const float* __restrict__ lin1_W, const float* __restrict__ lin1_b,
    const float* __restrict__ g_bn1, const float* __restrict__ b_bn1,
    const float* __restrict__ m_bn1, const float* __restrict__ v_bn1)
{
    const float eps = 1e-5f;
    int t = blockIdx.x * blockDim.x + threadIdx.x;
    if (t >= PREP_FOLD) {
        int u = t - PREP_FOLD;
        if (u < PREP_ZERO)
            ((float4*)g_agg)[u] = make_float4(0.f, 0.f, 0.f, 0.f);
        return;
    }
    if (t < NLAYER * FDIM * 128) {                     // W1: 24576
        int l = t / (FDIM * 128);
        int rem = t % (FDIM * 128);
        int j = rem % 128;
        float a = g1s[l * 128 + j] * rsqrtf(v1s[l * 128 + j] + eps);
        g_W1h[t] = __float2bfloat16(W1s[t] * a);
        if (rem < 128)
            g_b1f[l * 128 + rem] =
                (b1s[l * 128 + rem] - m1s[l * 128 + rem]) * a + bt1s[l * 128 + rem];
    } else if (t < 24576 + NLAYER * 128 * FDIM) {      // W2: 24576
        int u = t - 24576;
        int l = u / (128 * FDIM);
        int rem = u % (128 * FDIM);
        int j = rem % FDIM;
        float a = gcs[l * FDIM + j] * rsqrtf(vcs[l * FDIM + j] + eps);
        g_W2h[u] = __float2bfloat16(W2s[u] * a);
        if (rem < FDIM)
            g_b2f[l * FDIM + rem] =
                (b2s[l * FDIM + rem] - mcs[l * FDIM + rem]) * a + bcs[l * FDIM + rem];
    } else if (t < 49152 + FDIM * FDIM) {              // lin1f: 4096
        int u = t - 49152;
        int j = u % FDIM;
        float a = g_bn1[j] * rsqrtf(v_bn1[j] + eps);
        g_lin1f[u] = lin1_W[u] * a;
        if (u < FDIM)
            g_b1hf[u] = (lin1_b[u] - m_bn1[u]) * a + b_bn1[u];
    }
}

// ---------------- edge scatter: g_agg[dst] += x[src] (agg pre-zeroed) ----------------
__global__ void scatter_kernel(const int* __restrict__ ei,
                               const float* __restrict__ x)
{
    int t = blockIdx.x * blockDim.x + threadIdx.x;
    if (t >= (NEDGES / 4) * 16) return;
    int g = t >> 4;
    int q = t & 15;
    int4 ss = __ldg((const int4*)ei + g);
    int4 dd = __ldg((const int4*)(ei + NEDGES) + g);
    int s[4] = { ss.x, ss.y, ss.z, ss.w };
    int d[4] = { dd.x, dd.y, dd.z, dd.w };
    float4 v[4];
    #pragma unroll
    for (int i = 0; i < 4; i++) {
        bool ok = (unsigned)s[i] < NNODES;
        v[i] = ok ? __ldg((const float4*)x + (size_t)s[i] * 16 + q)
                  : make_float4(0.f, 0.f, 0.f, 0.f);
    }
    #pragma unroll
    for (int i = 0; i < 4; i++) {
        if ((unsigned)d[i] < NNODES && (unsigned)s[i] < NNODES) {
            float* p = g_agg + (size_t)d[i] * FDIM + q * 4;
            asm volatile("red.global.add.v4.f32 [%0], {%1,%2,%3,%4};"
                         :: "l"(p), "f"(v[i].x), "f"(v[i].y), "f"(v[i].z), "f"(v[i].w)
                         : "memory");
        }
    }
}

// ---------------- ptx helpers ----------------
__device__ __forceinline__ void ldsm_x4(uint32_t& r0, uint32_t& r1, uint32_t& r2,
                                        uint32_t& r3, uint32_t saddr) {
    asm volatile("ldmatrix.sync.aligned.m8n8.x4.shared.b16 {%0,%1,%2,%3}, [%4];"
                 : "=r"(r0), "=r"(r1), "=r"(r2), "=r"(r3) : "r"(saddr));
}
__device__ __forceinline__ void ldsm_x2_trans(uint32_t& r0, uint32_t& r1, uint32_t saddr) {
    asm volatile("ldmatrix.sync.aligned.m8n8.x2.trans.shared.b16 {%0,%1}, [%2];"
                 : "=r"(r0), "=r"(r1) : "r"(saddr));
}
__device__ __forceinline__ void mma_bf16(float& d0, float& d1, float& d2, float& d3,
                                         uint32_t a0, uint32_t a1, uint32_t a2, uint32_t a3,
                                         uint32_t b0, uint32_t b1) {
    asm volatile("mma.sync.aligned.m16n8k16.row.col.f32.bf16.bf16.f32 "
                 "{%0,%1,%2,%3}, {%4,%5,%6,%7}, {%8,%9}, {%0,%1,%2,%3};"
                 : "+f"(d0), "+f"(d1), "+f"(d2), "+f"(d3)
                 : "r"(a0), "r"(a1), "r"(a2), "r"(a3), "r"(b0), "r"(b1));
}

// ---------------- fused GIN MLP on bf16 mma.sync ----------------
// 128 nodes/CTA, 256 threads (8 warps, 16 rows each). h = agg + x computed here;
// agg tile rewritten to zero for next layer's scatter.
#define SH_LD  72     // bf16 elems: rows of 144B (16B aligned, ldmatrix conflict-free)
#define ST_LD  136    // bf16 elems: rows of 272B
#define SW1_LD 136
#define SW2_LD 72
// fp32 first for alignment: sB1(128) sB2(64), then bf16 tiles
#define OFF_B1  0
#define OFF_B2  128
#define OFF_H   192                         // floats; byte 768 (16B aligned)
#define MLP_SMEM_BYTES (768 + (128*SH_LD + 128*ST_LD + 64*SW1_LD + 128*SW2_LD) * 2)  // 89856

__global__ __launch_bounds__(256, 2)
void mlp_mma_kernel(const float* __restrict__ xin,
                    const __nv_bfloat16* __restrict__ W1h, const float* __restrict__ b1f,
                    const __nv_bfloat16* __restrict__ W2h, const float* __restrict__ b2f,
                    float* __restrict__ xout)
{
    extern __shared__ __align__(16) float smem_f[];
    float* sB1 = smem_f + OFF_B1;                         // 128
    float* sB2 = smem_f + OFF_B2;                         // 64
    __nv_bfloat16* sH  = (__nv_bfloat16*)(smem_f + OFF_H);  // 128 x 72
    __nv_bfloat16* sT  = sH + 128 * SH_LD;                  // 128 x 136
    __nv_bfloat16* sW1 = sT + 128 * ST_LD;                  // 64 x 136
    __nv_bfloat16* sW2 = sW1 + 64 * SW1_LD;                 // 128 x 72

    const int tid  = threadIdx.x;        // 256
    const int wid  = tid >> 5;           // 0..7
    const int lane = tid & 31;
    const int node0 = blockIdx.x * 128;
    const int r0 = wid * 16;

    // weights -> smem (vectorized 4x bf16)
    for (int i = tid; i < 64 * 32; i += 256) {         // W1: 64 x 128
        int k = i >> 5, n4 = (i & 31) * 4;
        uint2 w = *(const uint2*)(W1h + k * 128 + n4);
        *(uint2*)(sW1 + k * SW1_LD + n4) = w;
    }
    for (int i = tid; i < 128 * 16; i += 256) {        // W2: 128 x 64
        int k = i >> 4, n4 = (i & 15) * 4;
        uint2 w = *(const uint2*)(W2h + k * 64 + n4);
        *(uint2*)(sW2 + k * SW2_LD + n4) = w;
    }
    if (tid < 128) sB1[tid] = b1f[tid];
    else if (tid < 192) sB2[tid - 128] = b2f[tid - 128];

    // H = agg + x (fp32 -> bf16), and zero agg tile for next layer
    for (int i = tid; i < 128 * 16; i += 256) {
        int r = i >> 4, c4 = (i & 15) * 4;
        int node = node0 + r;
        float4 h = make_float4(0.f, 0.f, 0.f, 0.f);
        if (node < NNODES) {
            float4 a  = *(const float4*)(g_agg + (size_t)node * FDIM + c4);
            float4 xv = *(const float4*)(xin   + (size_t)node * FDIM + c4);
            h = make_float4(a.x + xv.x, a.y + xv.y, a.z + xv.z, a.w + xv.w);
            *(float4*)(g_agg + (size_t)node * FDIM + c4) = make_float4(0.f, 0.f, 0.f, 0.f);
        }
        __nv_bfloat162 p0 = __floats2bfloat162_rn(h.x, h.y);
        __nv_bfloat162 p1 = __floats2bfloat162_rn(h.z, h.w);
        *(uint32_t*)(sH + r * SH_LD + c4)     = *(uint32_t*)&p0;
        *(uint32_t*)(sH + r * SH_LD + c4 + 2) = *(uint32_t*)&p1;
    }
    __syncthreads();

    // fragment address lanes
    const int arow = (lane & 7) + ((lane >> 3) & 1) * 8;   // 0..15
    const int acol = (lane >> 4) * 8;                      // 0 or 8
    const int brow = lane & 15;                            // k-row for ldmatrix.trans
    const int drow = lane >> 2;                            // 0..7  (acc row)
    const int dcol = (lane & 3) * 2;                       // acc col pair

    // ---- stage 1: T[16x128] = relu(H[16x64] @ W1 + b1) per warp ----
    {
        uint32_t A[4][4];
        #pragma unroll
        for (int k0 = 0; k0 < 4; k0++) {
            uint32_t sa = (uint32_t)__cvta_generic_to_shared(
                sH + (r0 + arow) * SH_LD + k0 * 16 + acol);
            ldsm_x4(A[k0][0], A[k0][1], A[k0][2], A[k0][3], sa);
        }
        #pragma unroll
        for (int n0 = 0; n0 < 16; n0++) {
            float2 bias = *(const float2*)(sB1 + n0 * 8 + dcol);
            float d0 = bias.x, d1 = bias.y, d2 = bias.x, d3 = bias.y;
            #pragma unroll
            for (int k0 = 0; k0 < 4; k0++) {
                uint32_t b0, b1;
                uint32_t sb = (uint32_t)__cvta_generic_to_shared(
                    sW1 + (k0 * 16 + brow) * SW1_LD + n0 * 8);
                ldsm_x2_trans(b0, b1, sb);
                mma_bf16(d0, d1, d2, d3, A[k0][0], A[k0][1], A[k0][2], A[k0][3], b0, b1);
            }
            __nv_bfloat162 p0 = __floats2bfloat162_rn(fmaxf(d0, 0.f), fmaxf(d1, 0.f));
            __nv_bfloat162 p1 = __floats2bfloat162_rn(fmaxf(d2, 0.f), fmaxf(d3, 0.f));
            *(uint32_t*)(sT + (r0 + drow)     * ST_LD + n0 * 8 + dcol) = *(uint32_t*)&p0;
            *(uint32_t*)(sT + (r0 + drow + 8) * ST_LD + n0 * 8 + dcol) = *(uint32_t*)&p1;
        }
    }
    __syncwarp();   // warp-local T rows: order STS -> ldmatrix across lanes

    // ---- stage 2: O[16x64] = relu(T[16x128] @ W2 + b2) per warp ----
    {
        uint32_t A[8][4];
        #pragma unroll
        for (int k0 = 0; k0 < 8; k0++) {
            uint32_t sa = (uint32_t)__cvta_generic_to_shared(
                sT + (r0 + arow) * ST_LD + k0 * 16 + acol);
            ldsm_x4(A[k0][0], A[k0][1], A[k0][2], A[k0][3], sa);
        }
        #pragma unroll
        for (int n0 = 0; n0 < 8; n0++) {
            float2 bias = *(const float2*)(sB2 + n0 * 8 + dcol);
            float d0 = bias.x, d1 = bias.y, d2 = bias.x, d3 = bias.y;
            #pragma unroll
            for (int k0 = 0; k0 < 8; k0++) {
                uint32_t b0, b1;
                uint32_t sb = (uint32_t)__cvta_generic_to_shared(
                    sW2 + (k0 * 16 + brow) * SW2_LD + n0 * 8);
                ldsm_x2_trans(b0, b1, sb);
                mma_bf16(d0, d1, d2, d3, A[k0][0], A[k0][1], A[k0][2], A[k0][3], b0, b1);
            }
            int node = node0 + r0 + drow;
            if (node < NNODES)
                *(float2*)(xout + (size_t)node * FDIM + n0 * 8 + dcol) =
                    make_float2(fmaxf(d0, 0.f), fmaxf(d1, 0.f));
            if (node + 8 < NNODES)
                *(float2*)(xout + (size_t)(node + 8) * FDIM + n0 * 8 + dcol) =
                    make_float2(fmaxf(d2, 0.f), fmaxf(d3, 0.f));
        }
    }
}

// ---------------- head: relu(bn1(lin1 @ x)) -> lin2 -> log_softmax ----------------
#define HEAD_SMEM_FLOATS (4096 + 2560 + 4096 + 4096 + 2560 + 64 + 40 + 64 + 64)
__global__ void head_kernel(const float* __restrict__ xin,
                            const float* __restrict__ lin2_W,
                            const float* __restrict__ lin2_b,
                            float* __restrict__ out)
{
    extern __shared__ float smem[];
    float* sW1  = smem;            // 64x64 folded lin1
    float* sW2  = sW1 + 4096;      // 64x40
    float* sh   = sW2 + 2560;      // 64x64 input tile
    float* sh1  = sh + 4096;       // 64x64 hidden
    float* slog = sh1 + 4096;      // 64x40 logits
    float* sB1  = slog + 2560;     // 64
    float* sB2  = sB1 + 64;        // 40
    float* rmax = sB2 + 40;        // 64
    float* rlse = rmax + 64;       // 64

    int tid = threadIdx.x;         // 512
    int node0 = blockIdx.x * 64;

    for (int i = tid; i < 4096; i += 512) sW1[i] = g_lin1f[i];
    for (int i = tid; i < 2560; i += 512) sW2[i] = lin2_W[i];
    if (tid < 64) sB1[tid] = g_b1hf[tid];
    else if (tid < 104) sB2[tid - 64] = lin2_b[tid - 64];
    for (int i = tid; i < 4096; i += 512) {
        int node = node0 + (i >> 6);
        sh[i] = (node < NNODES) ? xin[(size_t)node * FDIM + (i & 63)] : 0.f;
    }
    __syncthreads();

    {
        int rb = (tid >> 4) * 2;
        int cb = (tid & 15) * 4;
        float acc[2][4];
        #pragma unroll
        for (int i = 0; i < 2; i++)
            #pragma unroll
            for (int j = 0; j < 4; j++) acc[i][j] = sB1[cb + j];
        #pragma unroll 4
        for (int k = 0; k < 64; k++) {
            float w[4];
            #pragma unroll
            for (int j = 0; j < 4; j++) w[j] = sW1[k * 64 + cb + j];
            #pragma unroll
            for (int i = 0; i < 2; i++) {
                float hv = sh[(rb + i) * 64 + k];
                #pragma unroll
                for (int j = 0; j < 4; j++) acc[i][j] = fmaf(hv, w[j], acc[i][j]);
            }
        }
        #pragma unroll
        for (int i = 0; i < 2; i++)
            #pragma unroll
            for (int j = 0; j < 4; j++)
                sh1[(rb + i) * 64 + cb + j] = fmaxf(acc[i][j], 0.f);
    }
    __syncthreads();

    {
        int r = tid >> 3;
        int c0 = (tid & 7) * 5;
        float acc[5];
        #pragma unroll
        for (int j = 0; j < 5; j++) acc[j] = sB2[c0 + j];
        #pragma unroll 4
        for (int k = 0; k < 64; k++) {
            float hv = sh1[r * 64 + k];
            #pragma unroll
            for (int j = 0; j < 5; j++) acc[j] = fmaf(hv, sW2[k * 40 + c0 + j], acc[j]);
        }
        #pragma unroll
        for (int j = 0; j < 5; j++) slog[r * 40 + c0 + j] = acc[j];
    }
    __syncthreads();

    if (tid < 64) {
        float m = -3.4e38f;
        #pragma unroll 8
        for (int c = 0; c < NCLS; c++) m = fmaxf(m, slog[tid * 40 + c]);
        float s = 0.f;
        #pragma unroll 8
        for (int c = 0; c < NCLS; c++) s += expf(slog[tid * 40 + c] - m);
        rmax[tid] = m;
        rlse[tid] = logf(s);
    }
    __syncthreads();

    for (int i = tid; i < 64 * NCLS; i += 512) {
        int r = i / NCLS;
        int node = node0 + r;
        if (node < NNODES)
            out[(size_t)node * NCLS + (i % NCLS)] = slog[i] - rmax[r] - rlse[r];
    }
}

// ---------------- launcher ----------------
extern "C" void kernel_launch(void* const* d_in, const int* in_sizes, int n_in,
                              void* d_out, int out_size)
{
    const float* x     = (const float*)d_in[0];
    const int*   ei    = (const int*)d_in[1];
    const float* W1s   = (const float*)d_in[2];
    const float* b1s   = (const float*)d_in[3];
    const float* g1s   = (const float*)d_in[4];
    const float* bt1s  = (const float*)d_in[5];
    const float* m1s   = (const float*)d_in[6];
    const float* v1s   = (const float*)d_in[7];
    const float* W2s   = (const float*)d_in[8];
    const float* b2s   = (const float*)d_in[9];
    const float* gcs   = (const float*)d_in[10];
    const float* bcs   = (const float*)d_in[11];
    const float* mcs   = (const float*)d_in[12];
    const float* vcs   = (const float*)d_in[13];
    const float* lin1_W = (const float*)d_in[14];
    const float* lin1_b = (const float*)d_in[15];
    const float* g_bn1 = (const float*)d_in[16];
    const float* b_bn1 = (const float*)d_in[17];
    const float* m_bn1 = (const float*)d_in[18];
    const float* v_bn1 = (const float*)d_in[19];
    const float* lin2_W = (const float*)d_in[20];
    const float* lin2_b = (const float*)d_in[21];

    float *xAp, *xBp, *b1fp, *b2fp;
    __nv_bfloat16 *W1hp, *W2hp;
    cudaGetSymbolAddress((void**)&xAp,  g_xA);
    cudaGetSymbolAddress((void**)&xBp,  g_xB);
    cudaGetSymbolAddress((void**)&W1hp, g_W1h);
    cudaGetSymbolAddress((void**)&W2hp, g_W2h);
    cudaGetSymbolAddress((void**)&b1fp, g_b1f);
    cudaGetSymbolAddress((void**)&b2fp, g_b2f);

    cudaFuncSetAttribute(mlp_mma_kernel, cudaFuncAttributeMaxDynamicSharedMemorySize,
                         MLP_SMEM_BYTES);
    cudaFuncSetAttribute(head_kernel, cudaFuncAttributeMaxDynamicSharedMemorySize,
                         HEAD_SMEM_FLOATS * 4);

    prep_kernel<<<(PREP_FOLD + PREP_ZERO + 255) / 256, 256>>>(
        W1s, b1s, g1s, bt1s, m1s, v1s, W2s, b2s, gcs, bcs, mcs, vcs,
        lin1_W, lin1_b, g_bn1, b_bn1, m_bn1, v_bn1);

    const int nblk128 = (NNODES + 127) / 128;
    const int nblk64  = (NNODES + 63) / 64;
    const int scatter_threads = (NEDGES / 4) * 16;
    const float* xin = x;
    float* bufs[2] = { xAp, xBp };
    for (int l = 0; l < NLAYER; l++) {
        scatter_kernel<<<(scatter_threads + 255) / 256, 256>>>(ei, xin);
        mlp_mma_kernel<<<nblk128, 256, MLP_SMEM_BYTES>>>(
            xin, W1hp + l * 8192, b1fp + l * 128, W2hp + l * 8192, b2fp + l * 64,
            bufs[l & 1]);
        xin = bufs[l & 1];
    }
    head_kernel<<<nblk64, 512, HEAD_SMEM_FLOATS * 4>>>(xin, lin2_W, lin2_b, (float*)d_out);
}

// round 15
// speedup vs baseline: 2.3040x; 1.4960x over previous
#include <cuda_runtime.h>
#include <cuda_bf16.h>
#include <cuda_fp16.h>
#include <cstdint>

#define NNODES 50000
#define NEDGES 800000
#define FDIM 64
#define NCLS 40
#define NLAYER 3

// ---------------- device scratch (no allocations allowed) ----------------
__device__ __align__(16) __half g_aggh[NNODES * FDIM];   // fp16 aggregation target
__device__ __align__(16) __half g_xh0[NNODES * FDIM];    // fp16 copy of input x
__device__ __align__(16) __half g_xhA[NNODES * FDIM];    // layer outputs (fp16)
__device__ __align__(16) __half g_xhB[NNODES * FDIM];
__device__ __align__(16) __nv_bfloat16 g_W1h[NLAYER * FDIM * 128];  // 3 x 64k x 128n
__device__ __align__(16) __nv_bfloat16 g_W2h[NLAYER * 128 * FDIM];  // 3 x 128k x 64n
__device__ __align__(16) float g_b1f[NLAYER * 128];
__device__ __align__(16) float g_b2f[NLAYER * FDIM];
__device__ __align__(16) float g_lin1f[FDIM * FDIM];
__device__ __align__(16) float g_b1hf[FDIM];

// ---------------- BN folding + agg zeroing + x -> fp16 conversion ----------------
#define PREP_FOLD 53280
#define PREP_ZERO 200000   // 3.2M halves as uint4 (16 halves/thread? no: 8 halves -> 400k; use 16/thread)
#define PREP_CONV 400000   // 3.2M floats, 8 per thread
__global__ void prep_kernel(
    const float* __restrict__ x,
    const float* __restrict__ W1s, const float* __restrict__ b1s,
    const float* __restrict__ g1s, const float* __restrict__ bt1s,
    const float* __restrict__ m1s, const float* __restrict__ v1s,
    const float* __restrict__ W2s, const float* __restrict__ b2s,
    const float* __restrict__ gcs, const float* __restrict__ bcs,
    const float* __restrict__ mcs, const float* __restrict__ vcs,
    const float* __restrict__ lin1_W, const float* __restrict__ lin1_b,
    const float* __restrict__ g_bn1, const float* __restrict__ b_bn1,
    const float* __restrict__ m_bn1, const float* __restrict__ v_bn1)
{
    const float eps = 1e-5f;
    int t = blockIdx.x * blockDim.x + threadIdx.x;
    if (t >= PREP_FOLD) {
        int u = t - PREP_FOLD;
        if (u < PREP_ZERO) {                    // zero agg: 16 halves per thread
            uint4 z = make_uint4(0, 0, 0, 0);
            ((uint4*)g_aggh)[u * 2]     = z;
            ((uint4*)g_aggh)[u * 2 + 1] = z;
        } else if (u < PREP_ZERO + PREP_CONV) { // convert x: 8 floats -> 8 halves
            int v = u - PREP_ZERO;
            float4 a = ((const float4*)x)[v * 2];
            float4 b = ((const float4*)x)[v * 2 + 1];
            __half2 h0 = __floats2half2_rn(a.x, a.y);
            __half2 h1 = __floats2half2_rn(a.z, a.w);
            __half2 h2 = __floats2half2_rn(b.x, b.y);
            __half2 h3 = __floats2half2_rn(b.z, b.w);
            uint4 o;
            o.x = *(uint32_t*)&h0; o.y = *(uint32_t*)&h1;
            o.z = *(uint32_t*)&h2; o.w = *(uint32_t*)&h3;
            ((uint4*)g_xh0)[v] = o;
        }
        return;
    }
    if (t < NLAYER * FDIM * 128) {                     // W1: 24576
        int l = t / (FDIM * 128);
        int rem = t % (FDIM * 128);
        int j = rem % 128;
        float a = g1s[l * 128 + j] * rsqrtf(v1s[l * 128 + j] + eps);
        g_W1h[t] = __float2bfloat16(W1s[t] * a);
        if (rem < 128)
            g_b1f[l * 128 + rem] =
                (b1s[l * 128 + rem] - m1s[l * 128 + rem]) * a + bt1s[l * 128 + rem];
    } else if (t < 24576 + NLAYER * 128 * FDIM) {      // W2: 24576
        int u = t - 24576;
        int l = u / (128 * FDIM);
        int rem = u % (128 * FDIM);
        int j = rem % FDIM;
        float a = gcs[l * FDIM + j] * rsqrtf(vcs[l * FDIM + j] + eps);
        g_W2h[u] = __float2bfloat16(W2s[u] * a);
        if (rem < FDIM)
            g_b2f[l * FDIM + rem] =
                (b2s[l * FDIM + rem] - mcs[l * FDIM + rem]) * a + bcs[l * FDIM + rem];
    } else if (t < 49152 + FDIM * FDIM) {              // lin1f: 4096
        int u = t - 49152;
        int j = u % FDIM;
        float a = g_bn1[j] * rsqrtf(v_bn1[j] + eps);
        g_lin1f[u] = lin1_W[u] * a;
        if (u < FDIM)
            g_b1hf[u] = (lin1_b[u] - m_bn1[u]) * a + b_bn1[u];
    }
}

// ---------------- edge scatter (fp16): g_aggh[dst] += xh[src] ----------------
// 8 threads/edge (16B chunk each), 4 edges/thread-group, v4.f16x2 reductions.
__global__ void scatter_kernel(const int* __restrict__ ei,
                               const __half* __restrict__ xh)
{
    int t = blockIdx.x * blockDim.x + threadIdx.x;
    if (t >= (NEDGES / 4) * 8) return;
    int g = t >> 3;
    int q = t & 7;
    int4 ss = __ldg((const int4*)ei + g);
    int4 dd = __ldg((const int4*)(ei + NEDGES) + g);
    int s[4] = { ss.x, ss.y, ss.z, ss.w };
    int d[4] = { dd.x, dd.y, dd.z, dd.w };
    uint4 v[4];
    #pragma unroll
    for (int i = 0; i < 4; i++) {
        bool ok = (unsigned)s[i] < NNODES;
        v[i] = ok ? __ldg((const uint4*)(xh + (size_t)s[i] * FDIM) + q)
                  : make_uint4(0, 0, 0, 0);
    }
    #pragma unroll
    for (int i = 0; i < 4; i++) {
        if ((unsigned)d[i] < NNODES && (unsigned)s[i] < NNODES) {
            __half* p = g_aggh + (size_t)d[i] * FDIM + q * 8;
            asm volatile("red.global.add.noftz.v4.f16x2 [%0], {%1,%2,%3,%4};"
                         :: "l"(p), "r"(v[i].x), "r"(v[i].y), "r"(v[i].z), "r"(v[i].w)
                         : "memory");
        }
    }
}

// ---------------- ptx helpers ----------------
__device__ __forceinline__ void ldsm_x4(uint32_t& r0, uint32_t& r1, uint32_t& r2,
                                        uint32_t& r3, uint32_t saddr) {
    asm volatile("ldmatrix.sync.aligned.m8n8.x4.shared.b16 {%0,%1,%2,%3}, [%4];"
                 : "=r"(r0), "=r"(r1), "=r"(r2), "=r"(r3) : "r"(saddr));
}
__device__ __forceinline__ void ldsm_x2_trans(uint32_t& r0, uint32_t& r1, uint32_t saddr) {
    asm volatile("ldmatrix.sync.aligned.m8n8.x2.trans.shared.b16 {%0,%1}, [%2];"
                 : "=r"(r0), "=r"(r1) : "r"(saddr));
}
__device__ __forceinline__ void mma_bf16(float& d0, float& d1, float& d2, float& d3,
                                         uint32_t a0, uint32_t a1, uint32_t a2, uint32_t a3,
                                         uint32_t b0, uint32_t b1) {
    asm volatile("mma.sync.aligned.m16n8k16.row.col.f32.bf16.bf16.f32 "
                 "{%0,%1,%2,%3}, {%4,%5,%6,%7}, {%8,%9}, {%0,%1,%2,%3};"
                 : "+f"(d0), "+f"(d1), "+f"(d2), "+f"(d3)
                 : "r"(a0), "r"(a1), "r"(a2), "r"(a3), "r"(b0), "r"(b1));
}

// ---------------- fused GIN MLP on bf16 mma.sync ----------------
#define SH_LD  72
#define ST_LD  136
#define SW1_LD 136
#define SW2_LD 72
#define OFF_B1  0
#define OFF_B2  128
#define OFF_H   192
#define MLP_SMEM_BYTES (768 + (128*SH_LD + 128*ST_LD + 64*SW1_LD + 128*SW2_LD) * 2)  // 89856

__global__ __launch_bounds__(256, 2)
void mlp_mma_kernel(const __half* __restrict__ xin,
                    const __nv_bfloat16* __restrict__ W1h, const float* __restrict__ b1f,
                    const __nv_bfloat16* __restrict__ W2h, const float* __restrict__ b2f,
                    __half* __restrict__ xout)
{
    extern __shared__ __align__(16) float smem_f[];
    float* sB1 = smem_f + OFF_B1;                           // 128
    float* sB2 = smem_f + OFF_B2;                           // 64
    __nv_bfloat16* sH  = (__nv_bfloat16*)(smem_f + OFF_H);  // 128 x 72
    __nv_bfloat16* sT  = sH + 128 * SH_LD;                  // 128 x 136
    __nv_bfloat16* sW1 = sT + 128 * ST_LD;                  // 64 x 136
    __nv_bfloat16* sW2 = sW1 + 64 * SW1_LD;                 // 128 x 72

    const int tid  = threadIdx.x;        // 256
    const int wid  = tid >> 5;           // 0..7
    const int lane = tid & 31;
    const int node0 = blockIdx.x * 128;
    const int r0 = wid * 16;

    // weights -> smem (vectorized 4x bf16)
    for (int i = tid; i < 64 * 32; i += 256) {         // W1: 64 x 128
        int k = i >> 5, n4 = (i & 31) * 4;
        uint2 w = *(const uint2*)(W1h + k * 128 + n4);
        *(uint2*)(sW1 + k * SW1_LD + n4) = w;
    }
    for (int i = tid; i < 128 * 16; i += 256) {        // W2: 128 x 64
        int k = i >> 4, n4 = (i & 15) * 4;
        uint2 w = *(const uint2*)(W2h + k * 64 + n4);
        *(uint2*)(sW2 + k * SW2_LD + n4) = w;
    }
    if (tid < 128) sB1[tid] = b1f[tid];
    else if (tid < 192) sB2[tid - 128] = b2f[tid - 128];

    // H = agg + x (fp16 -> fp32 add -> bf16), zero agg tile for next layer
    for (int i = tid; i < 128 * 8; i += 256) {     // 8 halves (16B) per iter
        int r = i >> 3, c8 = (i & 7) * 8;
        int node = node0 + r;
        uint32_t pk[4] = {0, 0, 0, 0};
        if (node < NNODES) {
            uint4 av = *(const uint4*)(g_aggh + (size_t)node * FDIM + c8);
            uint4 xv = *(const uint4*)(xin    + (size_t)node * FDIM + c8);
            const uint32_t* ap = &av.x;
            const uint32_t* xp = &xv.x;
            #pragma unroll
            for (int j = 0; j < 4; j++) {
                float2 fa = __half22float2(*(const __half2*)&ap[j]);
                float2 fx = __half22float2(*(const __half2*)&xp[j]);
                __nv_bfloat162 pb = __floats2bfloat162_rn(fa.x + fx.x, fa.y + fx.y);
                pk[j] = *(uint32_t*)&pb;
            }
            *(uint4*)(g_aggh + (size_t)node * FDIM + c8) = make_uint4(0, 0, 0, 0);
        }
        *(uint4*)(sH + r * SH_LD + c8) = make_uint4(pk[0], pk[1], pk[2], pk[3]);
    }
    __syncthreads();

    // fragment address lanes
    const int arow = (lane & 7) + ((lane >> 3) & 1) * 8;   // 0..15
    const int acol = (lane >> 4) * 8;                      // 0 or 8
    const int brow = lane & 15;                            // k-row for ldmatrix.trans
    const int drow = lane >> 2;                            // 0..7
    const int dcol = (lane & 3) * 2;

    // ---- stage 1: T[16x128] = relu(H[16x64] @ W1 + b1) per warp ----
    {
        uint32_t A[4][4];
        #pragma unroll
        for (int k0 = 0; k0 < 4; k0++) {
            uint32_t sa = (uint32_t)__cvta_generic_to_shared(
                sH + (r0 + arow) * SH_LD + k0 * 16 + acol);
            ldsm_x4(A[k0][0], A[k0][1], A[k0][2], A[k0][3], sa);
        }
        #pragma unroll
        for (int n0 = 0; n0 < 16; n0++) {
            float2 bias = *(const float2*)(sB1 + n0 * 8 + dcol);
            float d0 = bias.x, d1 = bias.y, d2 = bias.x, d3 = bias.y;
            #pragma unroll
            for (int k0 = 0; k0 < 4; k0++) {
                uint32_t b0, b1;
                uint32_t sb = (uint32_t)__cvta_generic_to_shared(
                    sW1 + (k0 * 16 + brow) * SW1_LD + n0 * 8);
                ldsm_x2_trans(b0, b1, sb);
                mma_bf16(d0, d1, d2, d3, A[k0][0], A[k0][1], A[k0][2], A[k0][3], b0, b1);
            }
            __nv_bfloat162 p0 = __floats2bfloat162_rn(fmaxf(d0, 0.f), fmaxf(d1, 0.f));
            __nv_bfloat162 p1 = __floats2bfloat162_rn(fmaxf(d2, 0.f), fmaxf(d3, 0.f));
            *(uint32_t*)(sT + (r0 + drow)     * ST_LD + n0 * 8 + dcol) = *(uint32_t*)&p0;
            *(uint32_t*)(sT + (r0 + drow + 8) * ST_LD + n0 * 8 + dcol) = *(uint32_t*)&p1;
        }
    }
    __syncwarp();

    // ---- stage 2: O[16x64] = relu(T[16x128] @ W2 + b2) per warp, fp16 out ----
    {
        uint32_t A[8][4];
        #pragma unroll
        for (int k0 = 0; k0 < 8; k0++) {
            uint32_t sa = (uint32_t)__cvta_generic_to_shared(
                sT + (r0 + arow) * ST_LD + k0 * 16 + acol);
            ldsm_x4(A[k0][0], A[k0][1], A[k0][2], A[k0][3], sa);
        }
        #pragma unroll
        for (int n0 = 0; n0 < 8; n0++) {
            float2 bias = *(const float2*)(sB2 + n0 * 8 + dcol);
            float d0 = bias.x, d1 = bias.y, d2 = bias.x, d3 = bias.y;
            #pragma unroll
            for (int k0 = 0; k0 < 8; k0++) {
                uint32_t b0, b1;
                uint32_t sb = (uint32_t)__cvta_generic_to_shared(
                    sW2 + (k0 * 16 + brow) * SW2_LD + n0 * 8);
                ldsm_x2_trans(b0, b1, sb);
                mma_bf16(d0, d1, d2, d3, A[k0][0], A[k0][1], A[k0][2], A[k0][3], b0, b1);
            }
            int node = node0 + r0 + drow;
            if (node < NNODES) {
                __half2 h = __floats2half2_rn(fmaxf(d0, 0.f), fmaxf(d1, 0.f));
                *(uint32_t*)(xout + (size_t)node * FDIM + n0 * 8 + dcol) = *(uint32_t*)&h;
            }
            if (node + 8 < NNODES) {
                __half2 h = __floats2half2_rn(fmaxf(d2, 0.f), fmaxf(d3, 0.f));
                *(uint32_t*)(xout + (size_t)(node + 8) * FDIM + n0 * 8 + dcol) = *(uint32_t*)&h;
            }
        }
    }
}

// ---------------- head: relu(bn1(lin1 @ x)) -> lin2 -> log_softmax ----------------
#define HEAD_SMEM_FLOATS (4096 + 2560 + 4096 + 4096 + 2560 + 64 + 40 + 64 + 64)
__global__ void head_kernel(const __half* __restrict__ xin,
                            const float* __restrict__ lin2_W,
                            const float* __restrict__ lin2_b,
                            float* __restrict__ out)
{
    extern __shared__ float smem[];
    float* sW1  = smem;            // 64x64 folded lin1
    float* sW2  = sW1 + 4096;      // 64x40
    float* sh   = sW2 + 2560;      // 64x64 input tile
    float* sh1  = sh + 4096;       // 64x64 hidden
    float* slog = sh1 + 4096;      // 64x40 logits
    float* sB1  = slog + 2560;     // 64
    float* sB2  = sB1 + 64;        // 40
    float* rmax = sB2 + 40;        // 64
    float* rlse = rmax + 64;       // 64

    int tid = threadIdx.x;         // 512
    int node0 = blockIdx.x * 64;

    for (int i = tid; i < 4096; i += 512) sW1[i] = g_lin1f[i];
    for (int i = tid; i < 2560; i += 512) sW2[i] = lin2_W[i];
    if (tid < 64) sB1[tid] = g_b1hf[tid];
    else if (tid < 104) sB2[tid - 64] = lin2_b[tid - 64];
    for (int i = tid; i < 4096; i += 512) {
        int node = node0 + (i >> 6);
        sh[i] = (node < NNODES) ? __half2float(xin[(size_t)node * FDIM + (i & 63)]) : 0.f;
    }
    __syncthreads();

    {
        int rb = (tid >> 4) * 2;
        int cb = (tid & 15) * 4;
        float acc[2][4];
        #pragma unroll
        for (int i = 0; i < 2; i++)
            #pragma unroll
            for (int j = 0; j < 4; j++) acc[i][j] = sB1[cb + j];
        #pragma unroll 4
        for (int k = 0; k < 64; k++) {
            float w[4];
            #pragma unroll
            for (int j = 0; j < 4; j++) w[j] = sW1[k * 64 + cb + j];
            #pragma unroll
            for (int i = 0; i < 2; i++) {
                float hv = sh[(rb + i) * 64 + k];
                #pragma unroll
                for (int j = 0; j < 4; j++) acc[i][j] = fmaf(hv, w[j], acc[i][j]);
            }
        }
        #pragma unroll
        for (int i = 0; i < 2; i++)
            #pragma unroll
            for (int j = 0; j < 4; j++)
                sh1[(rb + i) * 64 + cb + j] = fmaxf(acc[i][j], 0.f);
    }
    __syncthreads();

    {
        int r = tid >> 3;
        int c0 = (tid & 7) * 5;
        float acc[5];
        #pragma unroll
        for (int j = 0; j < 5; j++) acc[j] = sB2[c0 + j];
        #pragma unroll 4
        for (int k = 0; k < 64; k++) {
            float hv = sh1[r * 64 + k];
            #pragma unroll
            for (int j = 0; j < 5; j++) acc[j] = fmaf(hv, sW2[k * 40 + c0 + j], acc[j]);
        }
        #pragma unroll
        for (int j = 0; j < 5; j++) slog[r * 40 + c0 + j] = acc[j];
    }
    __syncthreads();

    if (tid < 64) {
        float m = -3.4e38f;
        #pragma unroll 8
        for (int c = 0; c < NCLS; c++) m = fmaxf(m, slog[tid * 40 + c]);
        float s = 0.f;
        #pragma unroll 8
        for (int c = 0; c < NCLS; c++) s += expf(slog[tid * 40 + c] - m);
        rmax[tid] = m;
        rlse[tid] = logf(s);
    }
    __syncthreads();

    for (int i = tid; i < 64 * NCLS; i += 512) {
        int r = i / NCLS;
        int node = node0 + r;
        if (node < NNODES)
            out[(size_t)node * NCLS + (i % NCLS)] = slog[i] - rmax[r] - rlse[r];
    }
}

// ---------------- launcher ----------------
extern "C" void kernel_launch(void* const* d_in, const int* in_sizes, int n_in,
                              void* d_out, int out_size)
{
    const float* x     = (const float*)d_in[0];
    const int*   ei    = (const int*)d_in[1];
    const float* W1s   = (const float*)d_in[2];
    const float* b1s   = (const float*)d_in[3];
    const float* g1s   = (const float*)d_in[4];
    const float* bt1s  = (const float*)d_in[5];
    const float* m1s   = (const float*)d_in[6];
    const float* v1s   = (const float*)d_in[7];
    const float* W2s   = (const float*)d_in[8];
    const float* b2s   = (const float*)d_in[9];
    const float* gcs   = (const float*)d_in[10];
    const float* bcs   = (const float*)d_in[11];
    const float* mcs   = (const float*)d_in[12];
    const float* vcs   = (const float*)d_in[13];
    const float* lin1_W = (const float*)d_in[14];
    const float* lin1_b = (const float*)d_in[15];
    const float* g_bn1 = (const float*)d_in[16];
    const float* b_bn1 = (const float*)d_in[17];
    const float* m_bn1 = (const float*)d_in[18];
    const float* v_bn1 = (const float*)d_in[19];
    const float* lin2_W = (const float*)d_in[20];
    const float* lin2_b = (const float*)d_in[21];

    __half *xh0p, *xhAp, *xhBp;
    float *b1fp, *b2fp;
    __nv_bfloat16 *W1hp, *W2hp;
    cudaGetSymbolAddress((void**)&xh0p, g_xh0);
    cudaGetSymbolAddress((void**)&xhAp, g_xhA);
    cudaGetSymbolAddress((void**)&xhBp, g_xhB);
    cudaGetSymbolAddress((void**)&W1hp, g_W1h);
    cudaGetSymbolAddress((void**)&W2hp, g_W2h);
    cudaGetSymbolAddress((void**)&b1fp, g_b1f);
    cudaGetSymbolAddress((void**)&b2fp, g_b2f);

    cudaFuncSetAttribute(mlp_mma_kernel, cudaFuncAttributeMaxDynamicSharedMemorySize,
                         MLP_SMEM_BYTES);
    cudaFuncSetAttribute(head_kernel, cudaFuncAttributeMaxDynamicSharedMemorySize,
                         HEAD_SMEM_FLOATS * 4);

    prep_kernel<<<(PREP_FOLD + PREP_ZERO + PREP_CONV + 255) / 256, 256>>>(
        x, W1s, b1s, g1s, bt1s, m1s, v1s, W2s, b2s, gcs, bcs, mcs, vcs,
        lin1_W, lin1_b, g_bn1, b_bn1, m_bn1, v_bn1);

    const int nblk128 = (NNODES + 127) / 128;
    const int nblk64  = (NNODES + 63) / 64;
    const int scatter_threads = (NEDGES / 4) * 8;
    const __half* xin = xh0p;
    __half* bufs[2] = { xhAp, xhBp };
    for (int l = 0; l < NLAYER; l++) {
        scatter_kernel<<<(scatter_threads + 255) / 256, 256>>>(ei, xin);
        mlp_mma_kernel<<<nblk128, 256, MLP_SMEM_BYTES>>>(
            xin, W1hp + l * 8192, b1fp + l * 128, W2hp + l * 8192, b2fp + l * 64,
            bufs[l & 1]);
        xin = bufs[l & 1];
    }
    head_kernel<<<nblk64, 512, HEAD_SMEM_FLOATS * 4>>>(xin, lin2_W, lin2_b, (float*)d_out);
}

// round 17
// speedup vs baseline: 3.2024x; 1.3899x over previous
#include <cuda_runtime.h>
#include <cuda_bf16.h>
#include <cuda_fp16.h>
#include <cstdint>

#define NNODES 50000
#define NEDGES 800000
#define FDIM 64
#define NCLS 40
#define NLAYER 3

// ---------------- device scratch (no allocations allowed) ----------------
__device__ __align__(16) __half g_aggh[NNODES * FDIM];   // fp16 aggregation target
__device__ __align__(16) __half g_xh0[NNODES * FDIM];    // fp16 copy of input x
__device__ __align__(16) __half g_xhA[NNODES * FDIM];    // layer outputs (fp16)
__device__ __align__(16) __half g_xhB[NNODES * FDIM];
__device__ __align__(16) __nv_bfloat16 g_W1h[NLAYER * FDIM * 128];  // 3 x 64k x 128n
__device__ __align__(16) __nv_bfloat16 g_W2h[NLAYER * 128 * FDIM];  // 3 x 128k x 64n
__device__ __align__(16) __nv_bfloat16 g_lin1h[FDIM * FDIM];        // 64k x 64n (BN folded)
__device__ __align__(16) __nv_bfloat16 g_lin2h[FDIM * NCLS];        // 64k x 40n
__device__ __align__(16) float g_b1f[NLAYER * 128];
__device__ __align__(16) float g_b2f[NLAYER * FDIM];
__device__ __align__(16) float g_b1hf[FDIM];

// ---------------- BN folding + agg zeroing + x -> fp16 conversion ----------------
#define PREP_FOLD 55808    // 24576 + 24576 + 4096 + 2560
#define PREP_ZERO 200000   // 3.2M halves, 16 per thread
#define PREP_CONV 400000   // 3.2M floats, 8 per thread
__global__ void prep_kernel(
    const float* __restrict__ x,
    const float* __restrict__ W1s, const float* __restrict__ b1s,
    const float* __restrict__ g1s, const float* __restrict__ bt1s,
    const float* __restrict__ m1s, const float* __restrict__ v1s,
    const float* __restrict__ W2s, const float* __restrict__ b2s,
    const float* __restrict__ gcs, const float* __restrict__ bcs,
    const float* __restrict__ mcs, const float* __restrict__ vcs,
    const float* __restrict__ lin1_W, const float* __restrict__ lin1_b,
    const float* __restrict__ g_bn1, const float* __restrict__ b_bn1,
    const float* __restrict__ m_bn1, const float* __restrict__ v_bn1,
    const float* __restrict__ lin2_W)
{
    const float eps = 1e-5f;
    int t = blockIdx.x * blockDim.x + threadIdx.x;
    if (t >= PREP_FOLD) {
        int u = t - PREP_FOLD;
        if (u < PREP_ZERO) {                    // zero agg: 16 halves per thread
            uint4 z = make_uint4(0, 0, 0, 0);
            ((uint4*)g_aggh)[u * 2]     = z;
            ((uint4*)g_aggh)[u * 2 + 1] = z;
        } else if (u < PREP_ZERO + PREP_CONV) { // convert x: 8 floats -> 8 halves
            int v = u - PREP_ZERO;
            float4 a = ((const float4*)x)[v * 2];
            float4 b = ((const float4*)x)[v * 2 + 1];
            __half2 h0 = __floats2half2_rn(a.x, a.y);
            __half2 h1 = __floats2half2_rn(a.z, a.w);
            __half2 h2 = __floats2half2_rn(b.x, b.y);
            __half2 h3 = __floats2half2_rn(b.z, b.w);
            uint4 o;
            o.x = *(uint32_t*)&h0; o.y = *(uint32_t*)&h1;
            o.z = *(uint32_t*)&h2; o.w = *(uint32_t*)&h3;
            ((uint4*)g_xh0)[v] = o;
        }
        return;
    }
    if (t < NLAYER * FDIM * 128) {                     // W1: 24576
        int l = t / (FDIM * 128);
        int rem = t % (FDIM * 128);
        int j = rem % 128;
        float a = g1s[l * 128 + j] * rsqrtf(v1s[l * 128 + j] + eps);
        g_W1h[t] = __float2bfloat16(W1s[t] * a);
        if (rem < 128)
            g_b1f[l * 128 + rem] =
                (b1s[l * 128 + rem] - m1s[l * 128 + rem]) * a + bt1s[l * 128 + rem];
    } else if (t < 24576 + NLAYER * 128 * FDIM) {      // W2: 24576
        int u = t - 24576;
        int l = u / (128 * FDIM);
        int rem = u % (128 * FDIM);
        int j = rem % FDIM;
        float a = gcs[l * FDIM + j] * rsqrtf(vcs[l * FDIM + j] + eps);
        g_W2h[u] = __float2bfloat16(W2s[u] * a);
        if (rem < FDIM)
            g_b2f[l * FDIM + rem] =
                (b2s[l * FDIM + rem] - mcs[l * FDIM + rem]) * a + bcs[l * FDIM + rem];
    } else if (t < 49152 + FDIM * FDIM) {              // lin1 (BN folded) -> bf16: 4096
        int u = t - 49152;
        int j = u % FDIM;
        float a = g_bn1[j] * rsqrtf(v_bn1[j] + eps);
        g_lin1h[u] = __float2bfloat16(lin1_W[u] * a);
        if (u < FDIM)
            g_b1hf[u] = (lin1_b[u] - m_bn1[u]) * a + b_bn1[u];
    } else {                                           // lin2 -> bf16: 2560
        int u = t - 53248;
        g_lin2h[u] = __float2bfloat16(lin2_W[u]);
    }
}

// ---------------- edge scatter (fp16): g_aggh[dst] += xh[src] ----------------
__global__ void scatter_kernel(const int* __restrict__ ei,
                               const __half* __restrict__ xh)
{
    int t = blockIdx.x * blockDim.x + threadIdx.x;
    if (t >= (NEDGES / 4) * 8) return;
    int g = t >> 3;
    int q = t & 7;
    int4 ss = __ldg((const int4*)ei + g);
    int4 dd = __ldg((const int4*)(ei + NEDGES) + g);
    int s[4] = { ss.x, ss.y, ss.z, ss.w };
    int d[4] = { dd.x, dd.y, dd.z, dd.w };
    uint4 v[4];
    #pragma unroll
    for (int i = 0; i < 4; i++) {
        bool ok = (unsigned)s[i] < NNODES;
        v[i] = ok ? __ldg((const uint4*)(xh + (size_t)s[i] * FDIM) + q)
                  : make_uint4(0, 0, 0, 0);
    }
    #pragma unroll
    for (int i = 0; i < 4; i++) {
        if ((unsigned)d[i] < NNODES && (unsigned)s[i] < NNODES) {
            __half* p = g_aggh + (size_t)d[i] * FDIM + q * 8;
            asm volatile("red.global.add.noftz.v4.f16x2 [%0], {%1,%2,%3,%4};"
                         :: "l"(p), "r"(v[i].x), "r"(v[i].y), "r"(v[i].z), "r"(v[i].w)
                         : "memory");
        }
    }
}

// ---------------- ptx helpers ----------------
__device__ __forceinline__ void ldsm_x4(uint32_t& r0, uint32_t& r1, uint32_t& r2,
                                        uint32_t& r3, uint32_t saddr) {
    asm volatile("ldmatrix.sync.aligned.m8n8.x4.shared.b16 {%0,%1,%2,%3}, [%4];"
                 : "=r"(r0), "=r"(r1), "=r"(r2), "=r"(r3) : "r"(saddr));
}
__device__ __forceinline__ void ldsm_x2_trans(uint32_t& r0, uint32_t& r1, uint32_t saddr) {
    asm volatile("ldmatrix.sync.aligned.m8n8.x2.trans.shared.b16 {%0,%1}, [%2];"
                 : "=r"(r0), "=r"(r1) : "r"(saddr));
}
// x4 trans: covers k16 x n16; lanes 0-15 -> n..n+7, lanes 16-31 -> n+8..n+15
__device__ __forceinline__ void ldsm_x4_trans(uint32_t& r0, uint32_t& r1, uint32_t& r2,
                                              uint32_t& r3, uint32_t saddr) {
    asm volatile("ldmatrix.sync.aligned.m8n8.x4.trans.shared.b16 {%0,%1,%2,%3}, [%4];"
                 : "=r"(r0), "=r"(r1), "=r"(r2), "=r"(r3) : "r"(saddr));
}
__device__ __forceinline__ void mma_bf16(float& d0, float& d1, float& d2, float& d3,
                                         uint32_t a0, uint32_t a1, uint32_t a2, uint32_t a3,
                                         uint32_t b0, uint32_t b1) {
    asm volatile("mma.sync.aligned.m16n8k16.row.col.f32.bf16.bf16.f32 "
                 "{%0,%1,%2,%3}, {%4,%5,%6,%7}, {%8,%9}, {%0,%1,%2,%3};"
                 : "+f"(d0), "+f"(d1), "+f"(d2), "+f"(d3)
                 : "r"(a0), "r"(a1), "r"(a2), "r"(a3), "r"(b0), "r"(b1));
}

// ---------------- fused GIN MLP (+optional head) on bf16 mma.sync ----------------
#define SH_LD  72
#define ST_LD  136
#define SW1_LD 136
#define SW2_LD 72
#define SL1_LD 72
#define SL2_LD 40
#define OFF_B1  0
#define OFF_B2  128
#define OFF_BH1 192
#define OFF_BH2 256
#define OFF_H   304                         // floats; byte 1216 (16B aligned)
#define MLP_BF16_ELEMS (128*SH_LD + 128*ST_LD + 64*SW1_LD + 128*SW2_LD + 64*SL1_LD + 64*SL2_LD)
#define MLP_SMEM_BYTES (OFF_H*4 + MLP_BF16_ELEMS*2)    // 1216 + 103424 = 104640

template<bool DO_HEAD>
__global__ __launch_bounds__(256, 2)
void mlp_mma_kernel(const __half* __restrict__ xin,
                    const __nv_bfloat16* __restrict__ W1h, const float* __restrict__ b1f,
                    const __nv_bfloat16* __restrict__ W2h, const float* __restrict__ b2f,
                    __half* __restrict__ xout,
                    const float* __restrict__ lin2_b, float* __restrict__ out)
{
    extern __shared__ __align__(16) float smem_f[];
    float* sB1  = smem_f + OFF_B1;                          // 128
    float* sB2  = smem_f + OFF_B2;                          // 64
    float* sBH1 = smem_f + OFF_BH1;                         // 64
    float* sBH2 = smem_f + OFF_BH2;                         // 40
    __nv_bfloat16* sH  = (__nv_bfloat16*)(smem_f + OFF_H);  // 128 x 72
    __nv_bfloat16* sT  = sH + 128 * SH_LD;                  // 128 x 136
    __nv_bfloat16* sW1 = sT + 128 * ST_LD;                  // 64 x 136
    __nv_bfloat16* sW2 = sW1 + 64 * SW1_LD;                 // 128 x 72
    __nv_bfloat16* sL1 = sW2 + 128 * SW2_LD;                // 64 x 72
    __nv_bfloat16* sL2 = sL1 + 64 * SL1_LD;                 // 64 x 40

    const int tid  = threadIdx.x;        // 256
    const int wid  = tid >> 5;           // 0..7
    const int lane = tid & 31;
    const int node0 = blockIdx.x * 128;
    const int r0 = wid * 16;

    // weights -> smem (vectorized 4x bf16)
    for (int i = tid; i < 64 * 32; i += 256) {         // W1: 64 x 128
        int k = i >> 5, n4 = (i & 31) * 4;
        uint2 w = *(const uint2*)(W1h + k * 128 + n4);
        *(uint2*)(sW1 + k * SW1_LD + n4) = w;
    }
    for (int i = tid; i < 128 * 16; i += 256) {        // W2: 128 x 64
        int k = i >> 4, n4 = (i & 15) * 4;
        uint2 w = *(const uint2*)(W2h + k * 64 + n4);
        *(uint2*)(sW2 + k * SW2_LD + n4) = w;
    }
    if (DO_HEAD) {
        for (int i = tid; i < 64 * 16; i += 256) {     // lin1: 64 x 64
            int k = i >> 4, n4 = (i & 15) * 4;
            uint2 w = *(const uint2*)(g_lin1h + k * 64 + n4);
            *(uint2*)(sL1 + k * SL1_LD + n4) = w;
        }
        for (int i = tid; i < 64 * 10; i += 256) {     // lin2: 64 x 40
            int k = i / 10, n4 = (i % 10) * 4;
            uint2 w = *(const uint2*)(g_lin2h + k * 40 + n4);
            *(uint2*)(sL2 + k * SL2_LD + n4) = w;
        }
        if (tid >= 192 && tid < 232) sBH2[tid - 192] = lin2_b[tid - 192];
    }
    if (tid < 128) sB1[tid] = b1f[tid];
    else if (tid < 192) sB2[tid - 128] = b2f[tid - 128];
    if (DO_HEAD && tid >= 232 && tid < 240) {
        // pad: nothing
    }
    if (DO_HEAD) {
        if (tid < 64) sBH1[tid] = g_b1hf[tid];   // note: also in tid<128 branch above (sB1) -- distinct smem, fine
    }

    // H = agg + x (fp16 -> fp32 add -> bf16), zero agg tile for next layer
    for (int i = tid; i < 128 * 8; i += 256) {     // 8 halves (16B) per iter
        int r = i >> 3, c8 = (i & 7) * 8;
        int node = node0 + r;
        uint32_t pk[4] = {0, 0, 0, 0};
        if (node < NNODES) {
            uint4 av = *(const uint4*)(g_aggh + (size_t)node * FDIM + c8);
            uint4 xv = *(const uint4*)(xin    + (size_t)node * FDIM + c8);
            const uint32_t* ap = &av.x;
            const uint32_t* xp = &xv.x;
            #pragma unroll
            for (int j = 0; j < 4; j++) {
                float2 fa = __half22float2(*(const __half2*)&ap[j]);
                float2 fx = __half22float2(*(const __half2*)&xp[j]);
                __nv_bfloat162 pb = __floats2bfloat162_rn(fa.x + fx.x, fa.y + fx.y);
                pk[j] = *(uint32_t*)&pb;
            }
            if (!DO_HEAD)
                *(uint4*)(g_aggh + (size_t)node * FDIM + c8) = make_uint4(0, 0, 0, 0);
        }
        *(uint4*)(sH + r * SH_LD + c8) = make_uint4(pk[0], pk[1], pk[2], pk[3]);
    }
    __syncthreads();

    // fragment address lanes
    const int arow = (lane & 7) + ((lane >> 3) & 1) * 8;   // 0..15
    const int acol = (lane >> 4) * 8;                      // 0 or 8
    const int brow = lane & 15;                            // k-row for trans loads
    const int bn8  = (lane >> 4) * 8;                      // +8 cols for x4.trans hi lanes
    const int drow = lane >> 2;                            // 0..7
    const int dcol = (lane & 3) * 2;

    // ---- stage 1: T[16x128] = relu(H[16x64] @ W1 + b1) per warp ----
    {
        uint32_t A[4][4];
        #pragma unroll
        for (int k0 = 0; k0 < 4; k0++) {
            uint32_t sa = (uint32_t)__cvta_generic_to_shared(
                sH + (r0 + arow) * SH_LD + k0 * 16 + acol);
            ldsm_x4(A[k0][0], A[k0][1], A[k0][2], A[k0][3], sa);
        }
        #pragma unroll
        for (int n1 = 0; n1 < 8; n1++) {               // 16 cols per iter
            float2 ba = *(const float2*)(sB1 + n1 * 16 + dcol);
            float2 bb = *(const float2*)(sB1 + n1 * 16 + 8 + dcol);
            float dA0 = ba.x, dA1 = ba.y, dA2 = ba.x, dA3 = ba.y;
            float dB0 = bb.x, dB1 = bb.y, dB2 = bb.x, dB3 = bb.y;
            #pragma unroll
            for (int k0 = 0; k0 < 4; k0++) {
                uint32_t b0, b1, b2, b3;
                uint32_t sb = (uint32_t)__cvta_generic_to_shared(
                    sW1 + (k0 * 16 + brow) * SW1_LD + n1 * 16 + bn8);
                ldsm_x4_trans(b0, b1, b2, b3, sb);
                mma_bf16(dA0, dA1, dA2, dA3, A[k0][0], A[k0][1], A[k0][2], A[k0][3], b0, b1);
                mma_bf16(dB0, dB1, dB2, dB3, A[k0][0], A[k0][1], A[k0][2], A[k0][3], b2, b3);
            }
            __nv_bfloat162 p;
            p = __floats2bfloat162_rn(fmaxf(dA0, 0.f), fmaxf(dA1, 0.f));
            *(uint32_t*)(sT + (r0 + drow)     * ST_LD + n1 * 16 + dcol) = *(uint32_t*)&p;
            p = __floats2bfloat162_rn(fmaxf(dA2, 0.f), fmaxf(dA3, 0.f));
            *(uint32_t*)(sT + (r0 + drow + 8) * ST_LD + n1 * 16 + dcol) = *(uint32_t*)&p;
            p = __floats2bfloat162_rn(fmaxf(dB0, 0.f), fmaxf(dB1, 0.f));
            *(uint32_t*)(sT + (r0 + drow)     * ST_LD + n1 * 16 + 8 + dcol) = *(uint32_t*)&p;
            p = __floats2bfloat162_rn(fmaxf(dB2, 0.f), fmaxf(dB3, 0.f));
            *(uint32_t*)(sT + (r0 + drow + 8) * ST_LD + n1 * 16 + 8 + dcol) = *(uint32_t*)&p;
        }
    }
    __syncwarp();

    // ---- stage 2: O[16x64] = relu(T[16x128] @ W2 + b2) per warp ----
    {
        uint32_t A[8][4];
        #pragma unroll
        for (int k0 = 0; k0 < 8; k0++) {
            uint32_t sa = (uint32_t)__cvta_generic_to_shared(
                sT + (r0 + arow) * ST_LD + k0 * 16 + acol);
            ldsm_x4(A[k0][0], A[k0][1], A[k0][2], A[k0][3], sa);
        }
        #pragma unroll
        for (int n1 = 0; n1 < 4; n1++) {
            float2 ba = *(const float2*)(sB2 + n1 * 16 + dcol);
            float2 bb = *(const float2*)(sB2 + n1 * 16 + 8 + dcol);
            float dA0 = ba.x, dA1 = ba.y, dA2 = ba.x, dA3 = ba.y;
            float dB0 = bb.x, dB1 = bb.y, dB2 = bb.x, dB3 = bb.y;
            #pragma unroll
            for (int k0 = 0; k0 < 8; k0++) {
                uint32_t b0, b1, b2, b3;
                uint32_t sb = (uint32_t)__cvta_generic_to_shared(
                    sW2 + (k0 * 16 + brow) * SW2_LD + n1 * 16 + bn8);
                ldsm_x4_trans(b0, b1, b2, b3, sb);
                mma_bf16(dA0, dA1, dA2, dA3, A[k0][0], A[k0][1], A[k0][2], A[k0][3], b0, b1);
                mma_bf16(dB0, dB1, dB2, dB3, A[k0][0], A[k0][1], A[k0][2], A[k0][3], b2, b3);
            }
            if (!DO_HEAD) {
                int node = node0 + r0 + drow;
                if (node < NNODES) {
                    __half2 h;
                    h = __floats2half2_rn(fmaxf(dA0, 0.f), fmaxf(dA1, 0.f));
                    *(uint32_t*)(xout + (size_t)node * FDIM + n1 * 16 + dcol) = *(uint32_t*)&h;
                    h = __floats2half2_rn(fmaxf(dB0, 0.f), fmaxf(dB1, 0.f));
                    *(uint32_t*)(xout + (size_t)node * FDIM + n1 * 16 + 8 + dcol) = *(uint32_t*)&h;
                }
                if (node + 8 < NNODES) {
                    __half2 h;
                    h = __floats2half2_rn(fmaxf(dA2, 0.f), fmaxf(dA3, 0.f));
                    *(uint32_t*)(xout + (size_t)(node + 8) * FDIM + n1 * 16 + dcol) = *(uint32_t*)&h;
                    h = __floats2half2_rn(fmaxf(dB2, 0.f), fmaxf(dB3, 0.f));
                    *(uint32_t*)(xout + (size_t)(node + 8) * FDIM + n1 * 16 + 8 + dcol) = *(uint32_t*)&h;
                }
            } else {
                // stash relu(O) bf16 into sH (warp-local rows) for the head
                __nv_bfloat162 p;
                p = __floats2bfloat162_rn(fmaxf(dA0, 0.f), fmaxf(dA1, 0.f));
                *(uint32_t*)(sH + (r0 + drow)     * SH_LD + n1 * 16 + dcol) = *(uint32_t*)&p;
                p = __floats2bfloat162_rn(fmaxf(dA2, 0.f), fmaxf(dA3, 0.f));
                *(uint32_t*)(sH + (r0 + drow + 8) * SH_LD + n1 * 16 + dcol) = *(uint32_t*)&p;
                p = __floats2bfloat162_rn(fmaxf(dB0, 0.f), fmaxf(dB1, 0.f));
                *(uint32_t*)(sH + (r0 + drow)     * SH_LD + n1 * 16 + 8 + dcol) = *(uint32_t*)&p;
                p = __floats2bfloat162_rn(fmaxf(dB2, 0.f), fmaxf(dB3, 0.f));
                *(uint32_t*)(sH + (r0 + drow + 8) * SH_LD + n1 * 16 + 8 + dcol) = *(uint32_t*)&p;
            }
        }
    }

    if (DO_HEAD) {
        __syncwarp();
        // ---- head stage 1: H1[16x64] = relu(O @ lin1f + b1h) ----
        {
            uint32_t A[4][4];
            #pragma unroll
            for (int k0 = 0; k0 < 4; k0++) {
                uint32_t sa = (uint32_t)__cvta_generic_to_shared(
                    sH + (r0 + arow) * SH_LD + k0 * 16 + acol);
                ldsm_x4(A[k0][0], A[k0][1], A[k0][2], A[k0][3], sa);
            }
            #pragma unroll
            for (int n1 = 0; n1 < 4; n1++) {
                float2 ba = *(const float2*)(sBH1 + n1 * 16 + dcol);
                float2 bb = *(const float2*)(sBH1 + n1 * 16 + 8 + dcol);
                float dA0 = ba.x, dA1 = ba.y, dA2 = ba.x, dA3 = ba.y;
                float dB0 = bb.x, dB1 = bb.y, dB2 = bb.x, dB3 = bb.y;
                #pragma unroll
                for (int k0 = 0; k0 < 4; k0++) {
                    uint32_t b0, b1, b2, b3;
                    uint32_t sb = (uint32_t)__cvta_generic_to_shared(
                        sL1 + (k0 * 16 + brow) * SL1_LD + n1 * 16 + bn8);
                    ldsm_x4_trans(b0, b1, b2, b3, sb);
                    mma_bf16(dA0, dA1, dA2, dA3, A[k0][0], A[k0][1], A[k0][2], A[k0][3], b0, b1);
                    mma_bf16(dB0, dB1, dB2, dB3, A[k0][0], A[k0][1], A[k0][2], A[k0][3], b2, b3);
                }
                __nv_bfloat162 p;
                p = __floats2bfloat162_rn(fmaxf(dA0, 0.f), fmaxf(dA1, 0.f));
                *(uint32_t*)(sT + (r0 + drow)     * ST_LD + n1 * 16 + dcol) = *(uint32_t*)&p;
                p = __floats2bfloat162_rn(fmaxf(dA2, 0.f), fmaxf(dA3, 0.f));
                *(uint32_t*)(sT + (r0 + drow + 8) * ST_LD + n1 * 16 + dcol) = *(uint32_t*)&p;
                p = __floats2bfloat162_rn(fmaxf(dB0, 0.f), fmaxf(dB1, 0.f));
                *(uint32_t*)(sT + (r0 + drow)     * ST_LD + n1 * 16 + 8 + dcol) = *(uint32_t*)&p;
                p = __floats2bfloat162_rn(fmaxf(dB2, 0.f), fmaxf(dB3, 0.f));
                *(uint32_t*)(sT + (r0 + drow + 8) * ST_LD + n1 * 16 + 8 + dcol) = *(uint32_t*)&p;
            }
        }
        __syncwarp();
        // ---- head stage 2: logits[16x40] = H1 @ lin2 + b, then log_softmax ----
        {
            uint32_t A[4][4];
            #pragma unroll
            for (int k0 = 0; k0 < 4; k0++) {
                uint32_t sa = (uint32_t)__cvta_generic_to_shared(
                    sT + (r0 + arow) * ST_LD + k0 * 16 + acol);
                ldsm_x4(A[k0][0], A[k0][1], A[k0][2], A[k0][3], sa);
            }
            float d[5][4];
            #pragma unroll
            for (int n0 = 0; n0 < 5; n0++) {
                float2 bias = *(const float2*)(sBH2 + n0 * 8 + dcol);
                d[n0][0] = bias.x; d[n0][1] = bias.y;
                d[n0][2] = bias.x; d[n0][3] = bias.y;
                #pragma unroll
                for (int k0 = 0; k0 < 4; k0++) {
                    uint32_t b0, b1;
                    uint32_t sb = (uint32_t)__cvta_generic_to_shared(
                        sL2 + (k0 * 16 + brow) * SL2_LD + n0 * 8);
                    ldsm_x2_trans(b0, b1, sb);
                    mma_bf16(d[n0][0], d[n0][1], d[n0][2], d[n0][3],
                             A[k0][0], A[k0][1], A[k0][2], A[k0][3], b0, b1);
                }
            }
            // log-softmax over 40 cols; rows owned by lane-quads (xor 1,2)
            float mA = -3.4e38f, mB = -3.4e38f;
            #pragma unroll
            for (int n0 = 0; n0 < 5; n0++) {
                mA = fmaxf(mA, fmaxf(d[n0][0], d[n0][1]));
                mB = fmaxf(mB, fmaxf(d[n0][2], d[n0][3]));
            }
            #pragma unroll
            for (int o = 1; o < 4; o <<= 1) {
                mA = fmaxf(mA, __shfl_xor_sync(0xffffffffu, mA, o));
                mB = fmaxf(mB, __shfl_xor_sync(0xffffffffu, mB, o));
            }
            float sA = 0.f, sB = 0.f;
            #pragma unroll
            for (int n0 = 0; n0 < 5; n0++) {
                sA += expf(d[n0][0] - mA) + expf(d[n0][1] - mA);
                sB += expf(d[n0][2] - mB) + expf(d[n0][3] - mB);
            }
            #pragma unroll
            for (int o = 1; o < 4; o <<= 1) {
                sA += __shfl_xor_sync(0xffffffffu, sA, o);
                sB += __shfl_xor_sync(0xffffffffu, sB, o);
            }
            float cA = mA + logf(sA);
            float cB = mB + logf(sB);
            int nodeA = node0 + r0 + drow;
            int nodeB = nodeA + 8;
            #pragma unroll
            for (int n0 = 0; n0 < 5; n0++) {
                if (nodeA < NNODES)
                    *(float2*)(out + (size_t)nodeA * NCLS + n0 * 8 + dcol) =
                        make_float2(d[n0][0] - cA, d[n0][1] - cA);
                if (nodeB < NNODES)
                    *(float2*)(out + (size_t)nodeB * NCLS + n0 * 8 + dcol) =
                        make_float2(d[n0][2] - cB, d[n0][3] - cB);
            }
        }
    }
}

// ---------------- launcher ----------------
extern "C" void kernel_launch(void* const* d_in, const int* in_sizes, int n_in,
                              void* d_out, int out_size)
{
    const float* x     = (const float*)d_in[0];
    const int*   ei    = (const int*)d_in[1];
    const float* W1s   = (const float*)d_in[2];
    const float* b1s   = (const float*)d_in[3];
    const float* g1s   = (const float*)d_in[4];
    const float* bt1s  = (const float*)d_in[5];
    const float* m1s   = (const float*)d_in[6];
    const float* v1s   = (const float*)d_in[7];
    const float* W2s   = (const float*)d_in[8];
    const float* b2s   = (const float*)d_in[9];
    const float* gcs   = (const float*)d_in[10];
    const float* bcs   = (const float*)d_in[11];
    const float* mcs   = (const float*)d_in[12];
    const float* vcs   = (const float*)d_in[13];
    const float* lin1_W = (const float*)d_in[14];
    const float* lin1_b = (const float*)d_in[15];
    const float* g_bn1 = (const float*)d_in[16];
    const float* b_bn1 = (const float*)d_in[17];
    const float* m_bn1 = (const float*)d_in[18];
    const float* v_bn1 = (const float*)d_in[19];
    const float* lin2_W = (const float*)d_in[20];
    const float* lin2_b = (const float*)d_in[21];

    __half *xh0p, *xhAp, *xhBp;
    float *b1fp, *b2fp;
    __nv_bfloat16 *W1hp, *W2hp;
    cudaGetSymbolAddress((void**)&xh0p, g_xh0);
    cudaGetSymbolAddress((void**)&xhAp, g_xhA);
    cudaGetSymbolAddress((void**)&xhBp, g_xhB);
    cudaGetSymbolAddress((void**)&W1hp, g_W1h);
    cudaGetSymbolAddress((void**)&W2hp, g_W2h);
    cudaGetSymbolAddress((void**)&b1fp, g_b1f);
    cudaGetSymbolAddress((void**)&b2fp, g_b2f);

    cudaFuncSetAttribute(mlp_mma_kernel<false>, cudaFuncAttributeMaxDynamicSharedMemorySize,
                         MLP_SMEM_BYTES);
    cudaFuncSetAttribute(mlp_mma_kernel<true>, cudaFuncAttributeMaxDynamicSharedMemorySize,
                         MLP_SMEM_BYTES);

    prep_kernel<<<(PREP_FOLD + PREP_ZERO + PREP_CONV + 255) / 256, 256>>>(
        x, W1s, b1s, g1s, bt1s, m1s, v1s, W2s, b2s, gcs, bcs, mcs, vcs,
        lin1_W, lin1_b, g_bn1, b_bn1, m_bn1, v_bn1, lin2_W);

    const int nblk128 = (NNODES + 127) / 128;
    const int scatter_threads = (NEDGES / 4) * 8;
    const __half* xin = xh0p;
    __half* bufs[2] = { xhAp, xhBp };
    for (int l = 0; l < NLAYER; l++) {
        scatter_kernel<<<(scatter_threads + 255) / 256, 256>>>(ei, xin);
        if (l < NLAYER - 1) {
            mlp_mma_kernel<false><<<nblk128, 256, MLP_SMEM_BYTES>>>(
                xin, W1hp + l * 8192, b1fp + l * 128, W2hp + l * 8192, b2fp + l * 64,
                bufs[l & 1], nullptr, nullptr);
            xin = bufs[l & 1];
        } else {
            mlp_mma_kernel<true><<<nblk128, 256, MLP_SMEM_BYTES>>>(
                xin, W1hp + l * 8192, b1fp + l * 128, W2hp + l * 8192, b2fp + l * 64,
                nullptr, lin2_b, (float*)d_out);
        }
    }
}